// round 6
// baseline (speedup 1.0000x reference)
#include <cuda_runtime.h>
#include <cuda_bf16.h>
#include <cfloat>

// Problem constants (fixed by the dataset)
#define NN 50000
#define EE 800000
#define ET (EE + NN)        // edges + self-loops
#define HXC 128             // H*C = 2*64
#define HIDD 64
#define OUTD 32

#define SCAN_BLK 256
#define NBLK ((NN + SCAN_BLK - 1) / SCAN_BLK)   // 196
#define AGG_BLOCKS 444      // 148 SMs * 3

// -------- scratch (device globals; no allocation allowed) --------
__device__ float g_xl[NN * HXC];     // transformed features [N,128]
__device__ float g_asrc[NN * 2];     // per-node per-head attention dots
__device__ float g_adst[NN * 2];
__device__ float g_h[NN * HIDD];     // post-FC hidden (layer-1 output)
__device__ int   g_deg[NN];          // CSR build
__device__ int   g_off[NN + 1];
__device__ int   g_cur[NN];
__device__ int   g_csr[ET];          // src index per (dst-sorted) edge
__device__ int   g_bsum[NBLK];

__device__ __forceinline__ float lrelu(float x) {
    return (x >= 0.f) ? x : 0.2f * x;
}

// ================= CSR build =================
__global__ void zero_deg_kernel() {
    int i = blockIdx.x * blockDim.x + threadIdx.x;
    if (i < NN) g_deg[i] = 1;   // self-loop
}
__global__ void hist_kernel(const int* __restrict__ ei) {
    int e = blockIdx.x * blockDim.x + threadIdx.x;
    if (e < EE) atomicAdd(&g_deg[ei[EE + e]], 1);
}
__global__ void scan1_kernel() {
    __shared__ int sh[SCAN_BLK];
    int i = blockIdx.x * SCAN_BLK + threadIdx.x;
    sh[threadIdx.x] = (i < NN) ? g_deg[i] : 0;
    __syncthreads();
    for (int o = SCAN_BLK / 2; o > 0; o >>= 1) {
        if (threadIdx.x < o) sh[threadIdx.x] += sh[threadIdx.x + o];
        __syncthreads();
    }
    if (threadIdx.x == 0) g_bsum[blockIdx.x] = sh[0];
}
__global__ void scan3_kernel() {
    __shared__ int sh[SCAN_BLK];
    __shared__ int base_sh;
    int t = threadIdx.x;
    int acc = 0;
    for (int i = t; i < blockIdx.x; i += SCAN_BLK) acc += g_bsum[i];
    sh[t] = acc;
    __syncthreads();
    for (int o = SCAN_BLK / 2; o > 0; o >>= 1) {
        if (t < o) sh[t] += sh[t + o];
        __syncthreads();
    }
    if (t == 0) base_sh = sh[0];
    __syncthreads();
    int base = base_sh;
    __syncthreads();
    int i = blockIdx.x * SCAN_BLK + t;
    int v = (i < NN) ? g_deg[i] : 0;
    sh[t] = v;
    __syncthreads();
    for (int o = 1; o < SCAN_BLK; o <<= 1) {
        int u = (t >= o) ? sh[t - o] : 0;
        __syncthreads();
        sh[t] += u;
        __syncthreads();
    }
    if (i < NN) {
        int off = base + sh[t] - v;
        g_off[i] = off;
        g_cur[i] = off;
        if (i == NN - 1) g_off[NN] = off + v;
    }
}
__global__ void scatter_kernel(const int* __restrict__ ei) {
    int e = blockIdx.x * blockDim.x + threadIdx.x;
    if (e >= ET) return;
    int s, d;
    if (e < EE) { s = ei[e]; d = ei[EE + e]; } else { s = d = e - EE; }
    int pos = atomicAdd(&g_cur[d], 1);
    g_csr[pos] = s;
}

// ================= K1: xl = x @ W + attention dots fused =================
__global__ void featatt_kernel(const float* __restrict__ x, const float* __restrict__ W,
                               const float* __restrict__ att_s, const float* __restrict__ att_d) {
    __shared__ float xs[64][64];      // 16 KB
    __shared__ float red[4][32];      // per-warp attention partials
    int tid = threadIdx.x;
    int n0 = blockIdx.x * 64;
    int lane = tid & 31, wid = tid >> 5;
    for (int i = tid; i < 64 * 64; i += 128) {
        int r = i >> 6, c = i & 63;
        xs[r][c] = (n0 + r < NN) ? x[(n0 + r) * 64 + c] : 0.f;
    }
    int col = tid;
    float wreg[64];
#pragma unroll
    for (int k = 0; k < 64; k++) wreg[k] = W[k * 128 + col];
    float asc = att_s[col], adc = att_d[col];
    __syncthreads();

    for (int t = 0; t < 4; t++) {
        float acc[16];
#pragma unroll
        for (int i = 0; i < 16; i++) acc[i] = 0.f;
#pragma unroll
        for (int i = 0; i < 16; i++) {
            const float4* xr = (const float4*)xs[t * 16 + i];
#pragma unroll
            for (int k4 = 0; k4 < 16; k4++) {
                float4 v = xr[k4];
                acc[i] += v.x * wreg[k4 * 4] + v.y * wreg[k4 * 4 + 1]
                        + v.z * wreg[k4 * 4 + 2] + v.w * wreg[k4 * 4 + 3];
            }
        }
        int nb = n0 + t * 16;
#pragma unroll
        for (int i = 0; i < 16; i++)
            if (nb + i < NN) g_xl[(nb + i) * HXC + col] = acc[i];
#pragma unroll
        for (int i = 0; i < 16; i++) {
            float s = acc[i] * asc, d = acc[i] * adc;
#pragma unroll
            for (int o = 16; o > 0; o >>= 1) {
                s += __shfl_xor_sync(0xffffffffu, s, o);
                d += __shfl_xor_sync(0xffffffffu, d, o);
            }
            if (lane == 0) { red[wid][i * 2] = s; red[wid][i * 2 + 1] = d; }
        }
        __syncthreads();
        if (tid < 64) {
            int i = tid >> 2, h = (tid >> 1) & 1, typ = tid & 1;
            int n = nb + i;
            if (n < NN) {
                float v = red[h * 2][i * 2 + typ] + red[h * 2 + 1][i * 2 + typ];
                if (typ == 0) g_asrc[n * 2 + h] = v;
                else          g_adst[n * 2 + h] = v;
            }
        }
        __syncthreads();
    }
}

// -------- warp gather+softmax for one dst node; returns elu(agg+bias) float4 --------
__device__ __forceinline__ float4 gather_node(int n, int lane, const float4* xl4,
                                              const float* bias_s) {
    int o0 = g_off[n], o1 = g_off[n + 1];
    float2 ad = ((const float2*)g_adst)[n];
    int h = lane >> 4;
    float4 acc = make_float4(0.f, 0.f, 0.f, 0.f);
    float dw0 = 0.f, dw1 = 0.f;
    for (int base = o0; base < o1; base += 32) {
        int c = min(32, o1 - base);
        int s_l = 0;
        float w0_l = 0.f, w1_l = 0.f;
        if (lane < c) {
            s_l = g_csr[base + lane];
            float2 as = ((const float2*)g_asrc)[s_l];
            w0_l = expf(lrelu(as.x + ad.x));
            w1_l = expf(lrelu(as.y + ad.y));
            dw0 += w0_l; dw1 += w1_l;
        }
        int nIter = (c + 3) & ~3;
        for (int j = 0; j < nIter; j += 4) {
            int   s[4];
            float w0[4], w1[4];
#pragma unroll
            for (int u = 0; u < 4; u++) {
                s[u]  = __shfl_sync(0xffffffffu, s_l, j + u);
                w0[u] = __shfl_sync(0xffffffffu, w0_l, j + u);
                w1[u] = __shfl_sync(0xffffffffu, w1_l, j + u);
            }
            float4 v[4];
#pragma unroll
            for (int u = 0; u < 4; u++) v[u] = xl4[s[u] * 32 + lane];
#pragma unroll
            for (int u = 0; u < 4; u++) {
                float w = h ? w1[u] : w0[u];
                acc.x += w * v[u].x; acc.y += w * v[u].y;
                acc.z += w * v[u].z; acc.w += w * v[u].w;
            }
        }
    }
#pragma unroll
    for (int o = 16; o > 0; o >>= 1) {
        dw0 += __shfl_xor_sync(0xffffffffu, dw0, o);
        dw1 += __shfl_xor_sync(0xffffffffu, dw1, o);
    }
    float inv = 1.f / ((h ? dw1 : dw0) + 1e-16f);
    const float4* b4 = (const float4*)bias_s;
    float4 bb = b4[lane];
    float4 r;
    r.x = acc.x * inv + bb.x; r.y = acc.y * inv + bb.y;
    r.z = acc.z * inv + bb.z; r.w = acc.w * inv + bb.w;
    r.x = (r.x > 0.f) ? r.x : expm1f(r.x);
    r.y = (r.y > 0.f) ? r.y : expm1f(r.y);
    r.z = (r.z > 0.f) ? r.z : expm1f(r.z);
    r.w = (r.w > 0.f) ? r.w : expm1f(r.w);
    return r;
}

// ================= K2: fused agg + ELU + FC (layer 1). grid-stride 32-node tiles =================
__global__ void aggpost_kernel(const float* __restrict__ bias,
                               const float* __restrict__ fcw,
                               const float* __restrict__ fcb) {
    __shared__ float tile[32][128];   // 16 KB
    __shared__ float part[32][64];    // 8 KB
    __shared__ float bias_s[128];
    __shared__ float fcb_s[64];
    int tid = threadIdx.x;            // 256
    int lane = tid & 31, wid = tid >> 5;
    int col = tid & 63, kh = (tid >> 6) & 1, grp = tid >> 7;
    if (tid < 128) bias_s[tid] = bias[tid];
    if (tid < 64) fcb_s[tid] = fcb[tid];
    __syncthreads();
    const float4* xl4 = (const float4*)g_xl;

    for (int tb = blockIdx.x * 32; tb < NN; tb += AGG_BLOCKS * 32) {
        // ---- gather phase: warp handles 4 nodes ----
        for (int i = 0; i < 4; i++) {
            int n = tb + i * 8 + wid;
            float4 r = make_float4(0.f, 0.f, 0.f, 0.f);
            if (n < NN) r = gather_node(n, lane, xl4, bias_s);
            ((float4*)tile[i * 8 + wid])[lane] = r;
        }
        __syncthreads();
        // ---- GEMM phase: 2 groups x 16 nodes, k split 2 ways ----
        float fwreg[64];
#pragma unroll
        for (int k = 0; k < 64; k++) fwreg[k] = fcw[(kh * 64 + k) * 64 + col];
        for (int ch = 0; ch < 2; ch++) {
            int r0 = grp * 16 + ch * 8;
            float a8[8];
#pragma unroll
            for (int j = 0; j < 8; j++) a8[j] = 0.f;
#pragma unroll
            for (int j = 0; j < 8; j++) {
                const float4* tr = (const float4*)&tile[r0 + j][kh * 64];
#pragma unroll
                for (int k4 = 0; k4 < 16; k4++) {
                    float4 v = tr[k4];
                    a8[j] += v.x * fwreg[k4 * 4] + v.y * fwreg[k4 * 4 + 1]
                           + v.z * fwreg[k4 * 4 + 2] + v.w * fwreg[k4 * 4 + 3];
                }
            }
            if (kh == 1) {
#pragma unroll
                for (int j = 0; j < 8; j++) part[r0 + j][col] = a8[j];
            }
            __syncthreads();
            if (kh == 0) {
#pragma unroll
                for (int j = 0; j < 8; j++) {
                    int n = tb + r0 + j;
                    if (n < NN) g_h[n * HIDD + col] = a8[j] + part[r0 + j][col] + fcb_s[col];
                }
            }
            __syncthreads();
        }
    }
}

// ================= K3: fused agg + ELU + FC + logits + gumbel softmax (layer 2) =================
__global__ void aggpostfinal_kernel(const float* __restrict__ bias,
                                    const float* __restrict__ fcw,
                                    const float* __restrict__ fcb,
                                    const float* __restrict__ ow,
                                    const float* __restrict__ ob,
                                    const float* __restrict__ gu,
                                    float* __restrict__ out) {
    __shared__ float tile[32][128];   // 16 KB
    __shared__ float part[32][64];    // 8 KB (GEMM partials, then h rows)
    __shared__ float ows[64 * 32];    // 8 KB
    __shared__ float bias_s[128];
    __shared__ float fcb_s[64];
    __shared__ float ob_s[32];
    int tid = threadIdx.x;            // 256
    int lane = tid & 31, wid = tid >> 5;
    int col = tid & 63, kh = (tid >> 6) & 1, grp = tid >> 7;
    for (int i = tid; i < 64 * 32; i += 256) ows[i] = ow[i];
    if (tid < 128) bias_s[tid] = bias[tid];
    if (tid < 64) fcb_s[tid] = fcb[tid];
    if (tid < 32) ob_s[tid] = ob[tid];
    __syncthreads();
    const float4* xl4 = (const float4*)g_xl;

    for (int tb = blockIdx.x * 32; tb < NN; tb += AGG_BLOCKS * 32) {
        for (int i = 0; i < 4; i++) {
            int n = tb + i * 8 + wid;
            float4 r = make_float4(0.f, 0.f, 0.f, 0.f);
            if (n < NN) r = gather_node(n, lane, xl4, bias_s);
            ((float4*)tile[i * 8 + wid])[lane] = r;
        }
        __syncthreads();
        float fwreg[64];
#pragma unroll
        for (int k = 0; k < 64; k++) fwreg[k] = fcw[(kh * 64 + k) * 64 + col];
        for (int ch = 0; ch < 2; ch++) {
            int r0 = grp * 16 + ch * 8;
            float a8[8];
#pragma unroll
            for (int j = 0; j < 8; j++) a8[j] = 0.f;
#pragma unroll
            for (int j = 0; j < 8; j++) {
                const float4* tr = (const float4*)&tile[r0 + j][kh * 64];
#pragma unroll
                for (int k4 = 0; k4 < 16; k4++) {
                    float4 v = tr[k4];
                    a8[j] += v.x * fwreg[k4 * 4] + v.y * fwreg[k4 * 4 + 1]
                           + v.z * fwreg[k4 * 4 + 2] + v.w * fwreg[k4 * 4 + 3];
                }
            }
            if (kh == 1) {
#pragma unroll
                for (int j = 0; j < 8; j++) part[r0 + j][col] = a8[j];
            }
            __syncthreads();
            if (kh == 0) {
#pragma unroll
                for (int j = 0; j < 8; j++)
                    part[r0 + j][col] = a8[j] + part[r0 + j][col] + fcb_s[col];  // h row
            }
            __syncthreads();
        }
        // ---- head: thread -> (node n = tid>>3, cols q*4..q*4+3) ----
        int n = tid >> 3, q = tid & 7;
        int gn = tb + n;
        float lg[4];
#pragma unroll
        for (int cc = 0; cc < 4; cc++) lg[cc] = ob_s[q * 4 + cc];
#pragma unroll 8
        for (int k = 0; k < 64; k++) {
            float hv = part[n][k];
#pragma unroll
            for (int cc = 0; cc < 4; cc++) lg[cc] += hv * ows[k * 32 + q * 4 + cc];
        }
        float4 u4 = (gn < NN) ? ((const float4*)gu)[gn * 8 + q]
                              : make_float4(0.5f, 0.5f, 0.5f, 0.5f);
        float z[4];
        float m = -FLT_MAX;
        float uu[4] = {u4.x, u4.y, u4.z, u4.w};
#pragma unroll
        for (int cc = 0; cc < 4; cc++) {
            float gg = -logf(-logf(uu[cc] + 1e-20f) + 1e-20f);
            z[cc] = lg[cc] + gg;
            m = fmaxf(m, z[cc]);
        }
        m = fmaxf(m, __shfl_xor_sync(0xffffffffu, m, 1, 8));
        m = fmaxf(m, __shfl_xor_sync(0xffffffffu, m, 2, 8));
        m = fmaxf(m, __shfl_xor_sync(0xffffffffu, m, 4, 8));
        float ssum = 0.f;
        float e[4];
#pragma unroll
        for (int cc = 0; cc < 4; cc++) { e[cc] = expf(z[cc] - m); ssum += e[cc]; }
        ssum += __shfl_xor_sync(0xffffffffu, ssum, 1, 8);
        ssum += __shfl_xor_sync(0xffffffffu, ssum, 2, 8);
        ssum += __shfl_xor_sync(0xffffffffu, ssum, 4, 8);
        if (gn < NN) {
            float inv = 1.f / ssum;
            float4 o4 = make_float4(e[0] * inv, e[1] * inv, e[2] * inv, e[3] * inv);
            ((float4*)out)[gn * 8 + q] = o4;
        }
        __syncthreads();   // part reused next tile iteration
    }
}

// ================= orchestration =================
extern "C" void kernel_launch(void* const* d_in, const int* in_sizes, int n_in,
                              void* d_out, int out_size) {
    const float* x      = (const float*)d_in[0];
    const int*   ei     = (const int*)d_in[1];
    const float* W0     = (const float*)d_in[2];
    const float* asrc0  = (const float*)d_in[3];
    const float* adst0  = (const float*)d_in[4];
    const float* bias0  = (const float*)d_in[5];
    const float* fcw0   = (const float*)d_in[6];
    const float* fcb0   = (const float*)d_in[7];
    const float* W1     = (const float*)d_in[8];
    const float* asrc1  = (const float*)d_in[9];
    const float* adst1  = (const float*)d_in[10];
    const float* bias1  = (const float*)d_in[11];
    const float* fcw1   = (const float*)d_in[12];
    const float* fcb1   = (const float*)d_in[13];
    const float* out_w  = (const float*)d_in[14];
    const float* out_b  = (const float*)d_in[15];
    const float* gu     = (const float*)d_in[16];
    float* out = (float*)d_out;

    float* hin;
    cudaGetSymbolAddress((void**)&hin, g_h);

    // CSR build
    zero_deg_kernel<<<(NN + 255) / 256, 256>>>();
    hist_kernel<<<(EE + 255) / 256, 256>>>(ei);
    scan1_kernel<<<NBLK, SCAN_BLK>>>();
    scan3_kernel<<<NBLK, SCAN_BLK>>>();
    scatter_kernel<<<(ET + 255) / 256, 256>>>(ei);

    // Layer 1
    featatt_kernel<<<(NN + 63) / 64, 128>>>(x, W0, asrc0, adst0);
    aggpost_kernel<<<AGG_BLOCKS, 256>>>(bias0, fcw0, fcb0);
    // Layer 2 (+ fused head)
    featatt_kernel<<<(NN + 63) / 64, 128>>>(hin, W1, asrc1, adst1);
    aggpostfinal_kernel<<<AGG_BLOCKS, 256>>>(bias1, fcw1, fcb1, out_w, out_b, gu, out);
}

// round 7
// speedup vs baseline: 1.0333x; 1.0333x over previous
#include <cuda_runtime.h>
#include <cuda_bf16.h>
#include <cfloat>

// Problem constants (fixed by the dataset)
#define NN 50000
#define EE 800000
#define ET (EE + NN)        // edges + self-loops
#define HXC 128             // H*C = 2*64
#define HIDD 64
#define OUTD 32

#define SCAN_BLK 256
#define NBLK ((NN + SCAN_BLK - 1) / SCAN_BLK)   // 196

// -------- scratch (device globals; no allocation allowed) --------
__device__ float g_xl[NN * HXC];     // transformed features [N,128]
__device__ float g_asrc[NN * 2];     // per-node per-head attention dots
__device__ float g_adst[NN * 2];
__device__ float g_agg[NN * HXC];    // normalized aggregation output
__device__ float g_h[NN * HIDD];     // post-FC hidden
__device__ int   g_deg[NN];          // CSR build (edge count, excl self-loop)
__device__ int   g_off[NN + 1];
__device__ int   g_cur[NN];
__device__ int   g_csr[ET];          // src index per (dst-sorted) edge

__device__ __forceinline__ float lrelu(float x) {
    return (x >= 0.f) ? x : 0.2f * x;
}

// ================= CSR build =================
__global__ void hist_kernel(const int* __restrict__ ei) {
    int e = blockIdx.x * blockDim.x + threadIdx.x;
    if (e < EE) atomicAdd(&g_deg[ei[EE + e]], 1);
}
// single-kernel scan: each block sums its preceding prefix itself.
// degree used = g_deg[i] + 1 (self-loop).
__global__ void scan_kernel() {
    __shared__ int sh[SCAN_BLK];
    __shared__ int base_sh;
    int t = threadIdx.x;
    int start = blockIdx.x * SCAN_BLK;
    int acc = 0;
    for (int i = t; i < start; i += SCAN_BLK) acc += g_deg[i] + 1;
    sh[t] = acc;
    __syncthreads();
    for (int o = SCAN_BLK / 2; o > 0; o >>= 1) {
        if (t < o) sh[t] += sh[t + o];
        __syncthreads();
    }
    if (t == 0) base_sh = sh[0];
    __syncthreads();
    int base = base_sh;
    __syncthreads();
    int i = start + t;
    int v = (i < NN) ? g_deg[i] + 1 : 0;
    sh[t] = v;
    __syncthreads();
    for (int o = 1; o < SCAN_BLK; o <<= 1) {
        int u = (t >= o) ? sh[t - o] : 0;
        __syncthreads();
        sh[t] += u;
        __syncthreads();
    }
    if (i < NN) {
        int off = base + sh[t] - v;
        g_off[i] = off;
        g_cur[i] = off;
        if (i == NN - 1) g_off[NN] = off + v;
    }
}
__global__ void scatter_kernel(const int* __restrict__ ei) {
    int e = blockIdx.x * blockDim.x + threadIdx.x;
    if (e >= ET) return;
    int s, d;
    if (e < EE) { s = ei[e]; d = ei[EE + e]; } else { s = d = e - EE; }
    int pos = atomicAdd(&g_cur[d], 1);
    g_csr[pos] = s;
}

// ================= K1: xl = x @ W + attention dots fused =================
__global__ void featatt_kernel(const float* __restrict__ x, const float* __restrict__ W,
                               const float* __restrict__ att_s, const float* __restrict__ att_d) {
    __shared__ float xs[64][64];      // 16 KB
    __shared__ float red[4][32];      // per-warp attention partials
    int tid = threadIdx.x;
    int n0 = blockIdx.x * 64;
    int lane = tid & 31, wid = tid >> 5;
    for (int i = tid; i < 64 * 64; i += 128) {
        int r = i >> 6, c = i & 63;
        xs[r][c] = (n0 + r < NN) ? x[(n0 + r) * 64 + c] : 0.f;
    }
    int col = tid;
    float wreg[64];
#pragma unroll
    for (int k = 0; k < 64; k++) wreg[k] = W[k * 128 + col];
    float asc = att_s[col], adc = att_d[col];
    __syncthreads();

    for (int t = 0; t < 4; t++) {
        float acc[16];
#pragma unroll
        for (int i = 0; i < 16; i++) acc[i] = 0.f;
#pragma unroll
        for (int i = 0; i < 16; i++) {
            const float4* xr = (const float4*)xs[t * 16 + i];
#pragma unroll
            for (int k4 = 0; k4 < 16; k4++) {
                float4 v = xr[k4];
                acc[i] += v.x * wreg[k4 * 4] + v.y * wreg[k4 * 4 + 1]
                        + v.z * wreg[k4 * 4 + 2] + v.w * wreg[k4 * 4 + 3];
            }
        }
        int nb = n0 + t * 16;
#pragma unroll
        for (int i = 0; i < 16; i++)
            if (nb + i < NN) g_xl[(nb + i) * HXC + col] = acc[i];
#pragma unroll
        for (int i = 0; i < 16; i++) {
            float s = acc[i] * asc, d = acc[i] * adc;
#pragma unroll
            for (int o = 16; o > 0; o >>= 1) {
                s += __shfl_xor_sync(0xffffffffu, s, o);
                d += __shfl_xor_sync(0xffffffffu, d, o);
            }
            if (lane == 0) { red[wid][i * 2] = s; red[wid][i * 2 + 1] = d; }
        }
        __syncthreads();
        if (tid < 64) {
            int i = tid >> 2, h = (tid >> 1) & 1, typ = tid & 1;
            int n = nb + i;
            if (n < NN) {
                float v = red[h * 2][i * 2 + typ] + red[h * 2 + 1][i * 2 + typ];
                if (typ == 0) g_asrc[n * 2 + h] = v;
                else          g_adst[n * 2 + h] = v;
            }
        }
        __syncthreads();
    }
}

// ================= K3: fused softmax + gather aggregation (warp per dst) =================
// 1 shfl per edge (src broadcast); each lane recomputes its head's weight from
// a broadcast asrc load + expf; denominator accumulates in-lane (no reduction).
__global__ void agg_kernel() {
    int warp = (blockIdx.x * blockDim.x + threadIdx.x) >> 5;
    int lane = threadIdx.x & 31;
    if (warp >= NN) return;
    int n = warp;
    int o0 = g_off[n], o1 = g_off[n + 1];
    float2 ad = ((const float2*)g_adst)[n];
    int h = lane >> 4;
    float adh = h ? ad.y : ad.x;
    float4 acc = make_float4(0.f, 0.f, 0.f, 0.f);
    float dsum = 0.f;
    const float4* xl4 = (const float4*)g_xl;
    const float2* as2 = (const float2*)g_asrc;

    for (int base = o0; base < o1; base += 32) {
        int c = min(32, o1 - base);
        int s_l = (lane < c) ? g_csr[base + lane] : -1;
        int nIter = (c + 3) & ~3;
        for (int j = 0; j < nIter; j += 4) {
            int s[4];
#pragma unroll
            for (int u = 0; u < 4; u++) s[u] = __shfl_sync(0xffffffffu, s_l, j + u);
            float w[4];
            float4 v[4];
#pragma unroll
            for (int u = 0; u < 4; u++) {
                int sm = (s[u] >= 0) ? s[u] : 0;
                float2 as = as2[sm];                 // warp-broadcast 8B load
                float ash = h ? as.y : as.x;
                w[u] = (s[u] >= 0) ? expf(lrelu(ash + adh)) : 0.f;
                v[u] = xl4[sm * 32 + lane];          // coalesced 512B row
            }
#pragma unroll
            for (int u = 0; u < 4; u++) {
                dsum += w[u];
                acc.x += w[u] * v[u].x; acc.y += w[u] * v[u].y;
                acc.z += w[u] * v[u].z; acc.w += w[u] * v[u].w;
            }
        }
    }
    float inv = 1.f / (dsum + 1e-16f);
    ((float4*)g_agg)[n * 32 + lane] =
        make_float4(acc.x * inv, acc.y * inv, acc.z * inv, acc.w * inv);
}

// ================= K4: h = elu(agg + bias) @ fcw + fcb  ([N,128] -> [N,64]) =================
__global__ void post_kernel(const float* __restrict__ bias,
                            const float* __restrict__ fcw,
                            const float* __restrict__ fcb) {
    __shared__ float tile[32][128];   // 16 KB
    __shared__ float part[32][64];    // 8 KB
    int tid = threadIdx.x;
    int n0 = blockIdx.x * 32;
    int col = tid & 63, kh = tid >> 6;
    float fwreg[64];
#pragma unroll
    for (int k = 0; k < 64; k++) fwreg[k] = fcw[(kh * 64 + k) * 64 + col];
    for (int i = tid; i < 32 * 128; i += 128) {
        int r = i >> 7, c = i & 127;
        float v = 0.f;
        if (n0 + r < NN) {
            v = g_agg[(n0 + r) * HXC + c] + bias[c];
            v = (v > 0.f) ? v : expm1f(v);   // ELU
        }
        tile[r][c] = v;
    }
    __syncthreads();
    float b = fcb[col];
    for (int ch = 0; ch < 4; ch++) {
        float acc[8];
#pragma unroll
        for (int j = 0; j < 8; j++) acc[j] = 0.f;
#pragma unroll
        for (int j = 0; j < 8; j++) {
            const float4* tr = (const float4*)&tile[ch * 8 + j][kh * 64];
#pragma unroll
            for (int k4 = 0; k4 < 16; k4++) {
                float4 v = tr[k4];
                acc[j] += v.x * fwreg[k4 * 4] + v.y * fwreg[k4 * 4 + 1]
                        + v.z * fwreg[k4 * 4 + 2] + v.w * fwreg[k4 * 4 + 3];
            }
        }
        if (kh == 1) {
#pragma unroll
            for (int j = 0; j < 8; j++) part[ch * 8 + j][col] = acc[j];
        }
        __syncthreads();
        if (kh == 0) {
#pragma unroll
            for (int j = 0; j < 8; j++) {
                int n = n0 + ch * 8 + j;
                if (n < NN) g_h[n * HIDD + col] = acc[j] + part[ch * 8 + j][col] + b;
            }
        }
    }
}

// ================= K5: layer-2 post + logits + gumbel softmax fused =================
__global__ void postfinal_kernel(const float* __restrict__ bias,
                                 const float* __restrict__ fcw,
                                 const float* __restrict__ fcb,
                                 const float* __restrict__ ow,
                                 const float* __restrict__ ob,
                                 const float* __restrict__ gu,
                                 float* __restrict__ out) {
    __shared__ float tile[32][128];   // 16 KB
    __shared__ float part[32][64];    // 8 KB
    __shared__ float h_s[32][64];     // 8 KB
    __shared__ float ows[64 * 32];    // 8 KB
    int tid = threadIdx.x;
    int n0 = blockIdx.x * 32;
    int col = tid & 63, kh = tid >> 6;
    for (int i = tid; i < 64 * 32; i += 128) ows[i] = ow[i];
    float fwreg[64];
#pragma unroll
    for (int k = 0; k < 64; k++) fwreg[k] = fcw[(kh * 64 + k) * 64 + col];
    for (int i = tid; i < 32 * 128; i += 128) {
        int r = i >> 7, c = i & 127;
        float v = 0.f;
        if (n0 + r < NN) {
            v = g_agg[(n0 + r) * HXC + c] + bias[c];
            v = (v > 0.f) ? v : expm1f(v);
        }
        tile[r][c] = v;
    }
    __syncthreads();
    float b = fcb[col];
    for (int ch = 0; ch < 4; ch++) {
        float acc[8];
#pragma unroll
        for (int j = 0; j < 8; j++) acc[j] = 0.f;
#pragma unroll
        for (int j = 0; j < 8; j++) {
            const float4* tr = (const float4*)&tile[ch * 8 + j][kh * 64];
#pragma unroll
            for (int k4 = 0; k4 < 16; k4++) {
                float4 v = tr[k4];
                acc[j] += v.x * fwreg[k4 * 4] + v.y * fwreg[k4 * 4 + 1]
                        + v.z * fwreg[k4 * 4 + 2] + v.w * fwreg[k4 * 4 + 3];
            }
        }
        if (kh == 1) {
#pragma unroll
            for (int j = 0; j < 8; j++) part[ch * 8 + j][col] = acc[j];
        }
        __syncthreads();
        if (kh == 0) {
#pragma unroll
            for (int j = 0; j < 8; j++)
                h_s[ch * 8 + j][col] = acc[j] + part[ch * 8 + j][col] + b;
        }
        __syncthreads();
    }
    // final head: thread t -> node n=t>>2, cols g*8..g*8+7
    int n = tid >> 2, g4 = tid & 3;
    int gn = n0 + n;
    float lg[8];
#pragma unroll
    for (int q = 0; q < 8; q++) lg[q] = ob[g4 * 8 + q];
#pragma unroll
    for (int k = 0; k < 64; k++) {
        float hv = h_s[n][k];
#pragma unroll
        for (int q = 0; q < 8; q++) lg[q] += hv * ows[k * 32 + g4 * 8 + q];
    }
    if (gn < NN) {
        float z[8];
        float m = -FLT_MAX;
#pragma unroll
        for (int q = 0; q < 8; q++) {
            float u = gu[gn * OUTD + g4 * 8 + q];
            float gg = -logf(-logf(u + 1e-20f) + 1e-20f);
            z[q] = lg[q] + gg;
            m = fmaxf(m, z[q]);
        }
        m = fmaxf(m, __shfl_xor_sync(0xffffffffu, m, 1, 4));
        m = fmaxf(m, __shfl_xor_sync(0xffffffffu, m, 2, 4));
        float ssum = 0.f;
        float e[8];
#pragma unroll
        for (int q = 0; q < 8; q++) { e[q] = expf(z[q] - m); ssum += e[q]; }
        ssum += __shfl_xor_sync(0xffffffffu, ssum, 1, 4);
        ssum += __shfl_xor_sync(0xffffffffu, ssum, 2, 4);
        float inv = 1.f / ssum;
#pragma unroll
        for (int q = 0; q < 8; q++) out[gn * OUTD + g4 * 8 + q] = e[q] * inv;
    }
}

// ================= orchestration =================
extern "C" void kernel_launch(void* const* d_in, const int* in_sizes, int n_in,
                              void* d_out, int out_size) {
    const float* x      = (const float*)d_in[0];
    const int*   ei     = (const int*)d_in[1];
    const float* W0     = (const float*)d_in[2];
    const float* asrc0  = (const float*)d_in[3];
    const float* adst0  = (const float*)d_in[4];
    const float* bias0  = (const float*)d_in[5];
    const float* fcw0   = (const float*)d_in[6];
    const float* fcb0   = (const float*)d_in[7];
    const float* W1     = (const float*)d_in[8];
    const float* asrc1  = (const float*)d_in[9];
    const float* adst1  = (const float*)d_in[10];
    const float* bias1  = (const float*)d_in[11];
    const float* fcw1   = (const float*)d_in[12];
    const float* fcb1   = (const float*)d_in[13];
    const float* out_w  = (const float*)d_in[14];
    const float* out_b  = (const float*)d_in[15];
    const float* gu     = (const float*)d_in[16];
    float* out = (float*)d_out;

    float* hin;
    cudaGetSymbolAddress((void**)&hin, g_h);
    int* degp;
    cudaGetSymbolAddress((void**)&degp, g_deg);

    // CSR build (edge_index identical for both layers)
    cudaMemsetAsync(degp, 0, NN * sizeof(int));
    hist_kernel<<<(EE + 255) / 256, 256>>>(ei);
    scan_kernel<<<NBLK, SCAN_BLK>>>();
    scatter_kernel<<<(ET + 255) / 256, 256>>>(ei);

    // Layer 1
    featatt_kernel<<<(NN + 63) / 64, 128>>>(x, W0, asrc0, adst0);
    agg_kernel<<<(NN + 7) / 8, 256>>>();
    post_kernel<<<(NN + 31) / 32, 128>>>(bias0, fcw0, fcb0);
    // Layer 2 (+ fused head)
    featatt_kernel<<<(NN + 63) / 64, 128>>>(hin, W1, asrc1, adst1);
    agg_kernel<<<(NN + 7) / 8, 256>>>();
    postfinal_kernel<<<(NN + 31) / 32, 128>>>(bias1, fcw1, fcb1, out_w, out_b, gu, out);
}

// round 8
// speedup vs baseline: 1.1376x; 1.1009x over previous
#include <cuda_runtime.h>
#include <cuda_bf16.h>
#include <cfloat>

// Problem constants (fixed by the dataset)
#define NN 50000
#define EE 800000
#define ET (EE + NN)        // edges + self-loops
#define HXC 128             // H*C = 2*64
#define HIDD 64
#define OUTD 32

#define SCAN_BLK 256
#define NBLK ((NN + SCAN_BLK - 1) / SCAN_BLK)   // 196

// -------- scratch (device globals; no allocation allowed) --------
__device__ float g_xl[NN * HXC];     // transformed features [N,128]
__device__ float g_asrc[NN * 2];     // per-node per-head attention dots
__device__ float g_adst[NN * 2];
__device__ float g_agg[NN * HXC];    // normalized aggregation output
__device__ float g_h[NN * HIDD];     // post-FC hidden
__device__ float g_wfold[64 * 4];    // W @ [att_src_h0|att_src_h1|att_dst_h0|att_dst_h1]
__device__ int   g_deg[NN];          // CSR build (edge count, excl self-loop)
__device__ int   g_off[NN + 1];
__device__ int   g_cur[NN];
__device__ int   g_csr[ET];          // src index per (dst-sorted) edge

__device__ __forceinline__ float lrelu(float x) {
    return (x >= 0.f) ? x : 0.2f * x;
}

// ================= CSR build =================
__global__ void hist_kernel(const int* __restrict__ ei) {
    int e = blockIdx.x * blockDim.x + threadIdx.x;
    if (e < EE) atomicAdd(&g_deg[ei[EE + e]], 1);
}
// single-kernel scan: each block sums its preceding prefix itself.
// degree used = g_deg[i] + 1 (self-loop).
__global__ void scan_kernel() {
    __shared__ int sh[SCAN_BLK];
    __shared__ int base_sh;
    int t = threadIdx.x;
    int start = blockIdx.x * SCAN_BLK;
    int acc = 0;
    for (int i = t; i < start; i += SCAN_BLK) acc += g_deg[i] + 1;
    sh[t] = acc;
    __syncthreads();
    for (int o = SCAN_BLK / 2; o > 0; o >>= 1) {
        if (t < o) sh[t] += sh[t + o];
        __syncthreads();
    }
    if (t == 0) base_sh = sh[0];
    __syncthreads();
    int base = base_sh;
    __syncthreads();
    int i = start + t;
    int v = (i < NN) ? g_deg[i] + 1 : 0;
    sh[t] = v;
    __syncthreads();
    for (int o = 1; o < SCAN_BLK; o <<= 1) {
        int u = (t >= o) ? sh[t - o] : 0;
        __syncthreads();
        sh[t] += u;
        __syncthreads();
    }
    if (i < NN) {
        int off = base + sh[t] - v;
        g_off[i] = off;
        g_cur[i] = off;
        if (i == NN - 1) g_off[NN] = off + v;
    }
}
__global__ void scatter_kernel(const int* __restrict__ ei) {
    int e = blockIdx.x * blockDim.x + threadIdx.x;
    if (e >= ET) return;
    int s, d;
    if (e < EE) { s = ei[e]; d = ei[EE + e]; } else { s = d = e - EE; }
    int pos = atomicAdd(&g_cur[d], 1);
    g_csr[pos] = s;
}

// ================= K0: fold attention vectors through W =================
// wfold[k][0] = sum_c W[k][c]      * att_s[c]       (head 0, src)
// wfold[k][1] = sum_c W[k][64+c]   * att_s[64+c]    (head 1, src)
// wfold[k][2,3] same with att_d.  One block, 256 threads = one output each.
__global__ void fold_kernel(const float* __restrict__ W,
                            const float* __restrict__ att_s,
                            const float* __restrict__ att_d) {
    int t = threadIdx.x;      // 256
    int k = t >> 2, j = t & 3;
    int h = j & 1;
    const float* av = (j < 2) ? att_s : att_d;
    float acc = 0.f;
#pragma unroll
    for (int c = 0; c < 64; c++)
        acc += W[k * 128 + h * 64 + c] * av[h * 64 + c];
    g_wfold[k * 4 + j] = acc;
}

// ================= K1: xl = x @ W; attention dots via folded vectors =================
// 64 nodes/block, 128 threads (thread = output col). No shfl reductions.
__global__ void featatt_kernel(const float* __restrict__ x, const float* __restrict__ W) {
    __shared__ float xs[64][68];      // padded rows (272B, 16B-aligned)
    __shared__ float wfs[64 * 4];
    int tid = threadIdx.x;
    int n0 = blockIdx.x * 64;
    for (int i = tid; i < 64 * 64; i += 128) {
        int r = i >> 6, c = i & 63;
        xs[r][c] = (n0 + r < NN) ? x[(n0 + r) * 64 + c] : 0.f;
    }
    wfs[tid] = g_wfold[tid];
    wfs[tid + 128] = g_wfold[tid + 128];
    int col = tid;
    float wreg[64];
#pragma unroll
    for (int k = 0; k < 64; k++) wreg[k] = W[k * 128 + col];
    __syncthreads();

    // ---- attention dots: thread -> (node r = tid>>1, src/dst pair = tid&1) ----
    {
        int r = tid >> 1, which = tid & 1;
        float o0 = 0.f, o1 = 0.f;
#pragma unroll
        for (int k = 0; k < 64; k++) {
            float xv = xs[r][k];
            o0 += xv * wfs[k * 4 + which * 2 + 0];
            o1 += xv * wfs[k * 4 + which * 2 + 1];
        }
        int n = n0 + r;
        if (n < NN) {
            if (which == 0) ((float2*)g_asrc)[n] = make_float2(o0, o1);
            else            ((float2*)g_adst)[n] = make_float2(o0, o1);
        }
    }

    // ---- main GEMM: 4 chunks x 16 nodes, fully unrolled accumulators ----
    for (int t = 0; t < 4; t++) {
        float acc[16];
#pragma unroll
        for (int i = 0; i < 16; i++) acc[i] = 0.f;
#pragma unroll
        for (int i = 0; i < 16; i++) {
            const float4* xr = (const float4*)&xs[t * 16 + i][0];
#pragma unroll
            for (int k4 = 0; k4 < 16; k4++) {
                float4 v = xr[k4];
                acc[i] += v.x * wreg[k4 * 4] + v.y * wreg[k4 * 4 + 1]
                        + v.z * wreg[k4 * 4 + 2] + v.w * wreg[k4 * 4 + 3];
            }
        }
        int nb = n0 + t * 16;
#pragma unroll
        for (int i = 0; i < 16; i++)
            if (nb + i < NN) g_xl[(nb + i) * HXC + col] = acc[i];
    }
}

// ================= K3: fused softmax + gather aggregation (warp per dst) =================
// R5 form: owning lane computes the 2 exps; s/w0/w1 broadcast via shfl; x4 unroll for MLP.
__global__ void agg_kernel() {
    int warp = (blockIdx.x * blockDim.x + threadIdx.x) >> 5;
    int lane = threadIdx.x & 31;
    if (warp >= NN) return;
    int n = warp;
    int o0 = g_off[n], o1 = g_off[n + 1];
    float2 ad = ((const float2*)g_adst)[n];
    int h = lane >> 4;
    float4 acc = make_float4(0.f, 0.f, 0.f, 0.f);
    float dw0 = 0.f, dw1 = 0.f;
    const float4* xl4 = (const float4*)g_xl;

    for (int base = o0; base < o1; base += 32) {
        int c = min(32, o1 - base);
        int s_l = 0;
        float w0_l = 0.f, w1_l = 0.f;
        if (lane < c) {
            s_l = g_csr[base + lane];
            float2 as = ((const float2*)g_asrc)[s_l];
            w0_l = expf(lrelu(as.x + ad.x));
            w1_l = expf(lrelu(as.y + ad.y));
            dw0 += w0_l; dw1 += w1_l;
        }
        int nIter = (c + 3) & ~3;        // padded lanes: w=0, s=0 (safe)
        for (int j = 0; j < nIter; j += 4) {
            int   s[4];
            float w0[4], w1[4];
#pragma unroll
            for (int u = 0; u < 4; u++) {
                s[u]  = __shfl_sync(0xffffffffu, s_l, j + u);
                w0[u] = __shfl_sync(0xffffffffu, w0_l, j + u);
                w1[u] = __shfl_sync(0xffffffffu, w1_l, j + u);
            }
            float4 v[4];
#pragma unroll
            for (int u = 0; u < 4; u++) v[u] = xl4[s[u] * 32 + lane];
#pragma unroll
            for (int u = 0; u < 4; u++) {
                float w = h ? w1[u] : w0[u];
                acc.x += w * v[u].x; acc.y += w * v[u].y;
                acc.z += w * v[u].z; acc.w += w * v[u].w;
            }
        }
    }
#pragma unroll
    for (int o = 16; o > 0; o >>= 1) {
        dw0 += __shfl_xor_sync(0xffffffffu, dw0, o);
        dw1 += __shfl_xor_sync(0xffffffffu, dw1, o);
    }
    float denom = (h ? dw1 : dw0) + 1e-16f;
    float inv = 1.f / denom;
    ((float4*)g_agg)[n * 32 + lane] =
        make_float4(acc.x * inv, acc.y * inv, acc.z * inv, acc.w * inv);
}

// ================= K4: h = elu(agg + bias) @ fcw + fcb  ([N,128] -> [N,64]) =================
__global__ void post_kernel(const float* __restrict__ bias,
                            const float* __restrict__ fcw,
                            const float* __restrict__ fcb) {
    __shared__ float tile[32][128];   // 16 KB
    __shared__ float part[32][64];    // 8 KB
    int tid = threadIdx.x;
    int n0 = blockIdx.x * 32;
    int col = tid & 63, kh = tid >> 6;
    float fwreg[64];
#pragma unroll
    for (int k = 0; k < 64; k++) fwreg[k] = fcw[(kh * 64 + k) * 64 + col];
    for (int i = tid; i < 32 * 128; i += 128) {
        int r = i >> 7, c = i & 127;
        float v = 0.f;
        if (n0 + r < NN) {
            v = g_agg[(n0 + r) * HXC + c] + bias[c];
            v = (v > 0.f) ? v : expm1f(v);   // ELU
        }
        tile[r][c] = v;
    }
    __syncthreads();
    float b = fcb[col];
    for (int ch = 0; ch < 4; ch++) {
        float acc[8];
#pragma unroll
        for (int j = 0; j < 8; j++) acc[j] = 0.f;
#pragma unroll
        for (int j = 0; j < 8; j++) {
            const float4* tr = (const float4*)&tile[ch * 8 + j][kh * 64];
#pragma unroll
            for (int k4 = 0; k4 < 16; k4++) {
                float4 v = tr[k4];
                acc[j] += v.x * fwreg[k4 * 4] + v.y * fwreg[k4 * 4 + 1]
                        + v.z * fwreg[k4 * 4 + 2] + v.w * fwreg[k4 * 4 + 3];
            }
        }
        if (kh == 1) {
#pragma unroll
            for (int j = 0; j < 8; j++) part[ch * 8 + j][col] = acc[j];
        }
        __syncthreads();
        if (kh == 0) {
#pragma unroll
            for (int j = 0; j < 8; j++) {
                int n = n0 + ch * 8 + j;
                if (n < NN) g_h[n * HIDD + col] = acc[j] + part[ch * 8 + j][col] + b;
            }
        }
    }
}

// ================= K5: layer-2 post + logits + gumbel softmax fused =================
__global__ void postfinal_kernel(const float* __restrict__ bias,
                                 const float* __restrict__ fcw,
                                 const float* __restrict__ fcb,
                                 const float* __restrict__ ow,
                                 const float* __restrict__ ob,
                                 const float* __restrict__ gu,
                                 float* __restrict__ out) {
    __shared__ float tile[32][128];   // 16 KB
    __shared__ float part[32][64];    // 8 KB
    __shared__ float h_s[32][64];     // 8 KB
    __shared__ float ows[64 * 32];    // 8 KB
    int tid = threadIdx.x;
    int n0 = blockIdx.x * 32;
    int col = tid & 63, kh = tid >> 6;
    for (int i = tid; i < 64 * 32; i += 128) ows[i] = ow[i];
    float fwreg[64];
#pragma unroll
    for (int k = 0; k < 64; k++) fwreg[k] = fcw[(kh * 64 + k) * 64 + col];
    for (int i = tid; i < 32 * 128; i += 128) {
        int r = i >> 7, c = i & 127;
        float v = 0.f;
        if (n0 + r < NN) {
            v = g_agg[(n0 + r) * HXC + c] + bias[c];
            v = (v > 0.f) ? v : expm1f(v);
        }
        tile[r][c] = v;
    }
    __syncthreads();
    float b = fcb[col];
    for (int ch = 0; ch < 4; ch++) {
        float acc[8];
#pragma unroll
        for (int j = 0; j < 8; j++) acc[j] = 0.f;
#pragma unroll
        for (int j = 0; j < 8; j++) {
            const float4* tr = (const float4*)&tile[ch * 8 + j][kh * 64];
#pragma unroll
            for (int k4 = 0; k4 < 16; k4++) {
                float4 v = tr[k4];
                acc[j] += v.x * fwreg[k4 * 4] + v.y * fwreg[k4 * 4 + 1]
                        + v.z * fwreg[k4 * 4 + 2] + v.w * fwreg[k4 * 4 + 3];
            }
        }
        if (kh == 1) {
#pragma unroll
            for (int j = 0; j < 8; j++) part[ch * 8 + j][col] = acc[j];
        }
        __syncthreads();
        if (kh == 0) {
#pragma unroll
            for (int j = 0; j < 8; j++)
                h_s[ch * 8 + j][col] = acc[j] + part[ch * 8 + j][col] + b;
        }
        __syncthreads();
    }
    // final head: thread t -> node n=t>>2, cols g*8..g*8+7
    int n = tid >> 2, g4 = tid & 3;
    int gn = n0 + n;
    float lg[8];
#pragma unroll
    for (int q = 0; q < 8; q++) lg[q] = ob[g4 * 8 + q];
#pragma unroll
    for (int k = 0; k < 64; k++) {
        float hv = h_s[n][k];
#pragma unroll
        for (int q = 0; q < 8; q++) lg[q] += hv * ows[k * 32 + g4 * 8 + q];
    }
    if (gn < NN) {
        float z[8];
        float m = -FLT_MAX;
#pragma unroll
        for (int q = 0; q < 8; q++) {
            float u = gu[gn * OUTD + g4 * 8 + q];
            float gg = -logf(-logf(u + 1e-20f) + 1e-20f);
            z[q] = lg[q] + gg;
            m = fmaxf(m, z[q]);
        }
        m = fmaxf(m, __shfl_xor_sync(0xffffffffu, m, 1, 4));
        m = fmaxf(m, __shfl_xor_sync(0xffffffffu, m, 2, 4));
        float ssum = 0.f;
        float e[8];
#pragma unroll
        for (int q = 0; q < 8; q++) { e[q] = expf(z[q] - m); ssum += e[q]; }
        ssum += __shfl_xor_sync(0xffffffffu, ssum, 1, 4);
        ssum += __shfl_xor_sync(0xffffffffu, ssum, 2, 4);
        float inv = 1.f / ssum;
#pragma unroll
        for (int q = 0; q < 8; q++) out[gn * OUTD + g4 * 8 + q] = e[q] * inv;
    }
}

// ================= orchestration =================
extern "C" void kernel_launch(void* const* d_in, const int* in_sizes, int n_in,
                              void* d_out, int out_size) {
    const float* x      = (const float*)d_in[0];
    const int*   ei     = (const int*)d_in[1];
    const float* W0     = (const float*)d_in[2];
    const float* asrc0  = (const float*)d_in[3];
    const float* adst0  = (const float*)d_in[4];
    const float* bias0  = (const float*)d_in[5];
    const float* fcw0   = (const float*)d_in[6];
    const float* fcb0   = (const float*)d_in[7];
    const float* W1     = (const float*)d_in[8];
    const float* asrc1  = (const float*)d_in[9];
    const float* adst1  = (const float*)d_in[10];
    const float* bias1  = (const float*)d_in[11];
    const float* fcw1   = (const float*)d_in[12];
    const float* fcb1   = (const float*)d_in[13];
    const float* out_w  = (const float*)d_in[14];
    const float* out_b  = (const float*)d_in[15];
    const float* gu     = (const float*)d_in[16];
    float* out = (float*)d_out;

    float* hin;
    cudaGetSymbolAddress((void**)&hin, g_h);
    int* degp;
    cudaGetSymbolAddress((void**)&degp, g_deg);

    // CSR build (edge_index identical for both layers)
    cudaMemsetAsync(degp, 0, NN * sizeof(int));
    hist_kernel<<<(EE + 255) / 256, 256>>>(ei);
    scan_kernel<<<NBLK, SCAN_BLK>>>();
    scatter_kernel<<<(ET + 255) / 256, 256>>>(ei);

    // Layer 1
    fold_kernel<<<1, 256>>>(W0, asrc0, adst0);
    featatt_kernel<<<(NN + 63) / 64, 128>>>(x, W0);
    agg_kernel<<<(NN + 7) / 8, 256>>>();
    post_kernel<<<(NN + 31) / 32, 128>>>(bias0, fcw0, fcb0);
    // Layer 2 (+ fused head)
    fold_kernel<<<1, 256>>>(W1, asrc1, adst1);
    featatt_kernel<<<(NN + 63) / 64, 128>>>(hin, W1);
    agg_kernel<<<(NN + 7) / 8, 256>>>();
    postfinal_kernel<<<(NN + 31) / 32, 128>>>(bias1, fcw1, fcb1, out_w, out_b, gu, out);
}

// round 9
// speedup vs baseline: 1.1837x; 1.0406x over previous
#include <cuda_runtime.h>
#include <cuda_bf16.h>
#include <cfloat>

// Problem constants (fixed by the dataset)
#define NN 50000
#define EE 800000
#define ET (EE + NN)        // edges + self-loops
#define HXC 128             // H*C = 2*64
#define HIDD 64
#define OUTD 32

#define SCAN_BLK 256
#define NBLK ((NN + SCAN_BLK - 1) / SCAN_BLK)   // 196
#define HB ((EE + 255) / 256)                   // 3125 hist blocks
#define SB ((ET + 255) / 256)                   // 3321 scatter blocks
#define FB ((NN + 63) / 64)                     // 782 featatt blocks

// -------- scratch (device globals; no allocation allowed) --------
__device__ float g_xl[NN * HXC];     // transformed features [N,128]
__device__ float g_asrc[NN * 2];     // per-node per-head attention dots
__device__ float g_adst[NN * 2];
__device__ float g_agg[NN * HXC];    // normalized aggregation output
__device__ float g_h[NN * HIDD];     // post-FC hidden
__device__ float g_wfold[2][64 * 4]; // per-layer W @ [att_src|att_dst] folds
__device__ int   g_deg[NN];          // CSR build (edge count, excl self-loop)
__device__ int   g_off[NN + 1];
__device__ int   g_cur[NN];
__device__ int   g_csr[ET];          // src index per (dst-sorted) edge

__device__ __forceinline__ float lrelu(float x) {
    return (x >= 0.f) ? x : 0.2f * x;
}

// ================= K2: hist + both attention folds (merged) =================
// blocks 0,1: fold for layer 0/1.  blocks 2..HB+1: histogram.
__global__ void histfold_kernel(const int* __restrict__ ei,
                                const float* __restrict__ W0,
                                const float* __restrict__ as0, const float* __restrict__ ad0,
                                const float* __restrict__ W1,
                                const float* __restrict__ as1, const float* __restrict__ ad1) {
    int b = blockIdx.x;
    if (b < 2) {
        const float* W  = b ? W1 : W0;
        const float* as_ = b ? as1 : as0;
        const float* ad_ = b ? ad1 : ad0;
        int t = threadIdx.x;      // 256
        int k = t >> 2, j = t & 3;
        int h = j & 1;
        const float* av = (j < 2) ? as_ : ad_;
        float acc = 0.f;
#pragma unroll
        for (int c = 0; c < 64; c++)
            acc += W[k * 128 + h * 64 + c] * av[h * 64 + c];
        g_wfold[b][k * 4 + j] = acc;
    } else {
        int e = (b - 2) * 256 + threadIdx.x;
        if (e < EE) atomicAdd(&g_deg[ei[EE + e]], 1);
    }
}

// ================= K3: single-kernel scan (self-loop folded as deg+1) =================
__global__ void scan_kernel() {
    __shared__ int sh[SCAN_BLK];
    __shared__ int base_sh;
    int t = threadIdx.x;
    int start = blockIdx.x * SCAN_BLK;
    int acc = 0;
    for (int i = t; i < start; i += SCAN_BLK) acc += g_deg[i] + 1;
    sh[t] = acc;
    __syncthreads();
    for (int o = SCAN_BLK / 2; o > 0; o >>= 1) {
        if (t < o) sh[t] += sh[t + o];
        __syncthreads();
    }
    if (t == 0) base_sh = sh[0];
    __syncthreads();
    int base = base_sh;
    __syncthreads();
    int i = start + t;
    int v = (i < NN) ? g_deg[i] + 1 : 0;
    sh[t] = v;
    __syncthreads();
    for (int o = 1; o < SCAN_BLK; o <<= 1) {
        int u = (t >= o) ? sh[t - o] : 0;
        __syncthreads();
        sh[t] += u;
        __syncthreads();
    }
    if (i < NN) {
        int off = base + sh[t] - v;
        g_off[i] = off;
        g_cur[i] = off;
        if (i == NN - 1) g_off[NN] = off + v;
    }
}

// ================= featatt body: xl = x @ W; attention dots via fold =================
__device__ __forceinline__ void featatt_body(const float* __restrict__ x,
                                             const float* __restrict__ W,
                                             const float* __restrict__ wf,
                                             int bidx) {
    __shared__ float xs[64][68];      // padded rows
    __shared__ float wfs[64 * 4];
    int tid = threadIdx.x;            // 128 active
    int n0 = bidx * 64;
    for (int i = tid; i < 64 * 64; i += 128) {
        int r = i >> 6, c = i & 63;
        xs[r][c] = (n0 + r < NN) ? x[(n0 + r) * 64 + c] : 0.f;
    }
    wfs[tid] = wf[tid];
    wfs[tid + 128] = wf[tid + 128];
    int col = tid;
    float wreg[64];
#pragma unroll
    for (int k = 0; k < 64; k++) wreg[k] = W[k * 128 + col];
    __syncthreads();

    // attention dots: thread -> (node r = tid>>1, src/dst = tid&1)
    {
        int r = tid >> 1, which = tid & 1;
        float o0 = 0.f, o1 = 0.f;
#pragma unroll
        for (int k = 0; k < 64; k++) {
            float xv = xs[r][k];
            o0 += xv * wfs[k * 4 + which * 2 + 0];
            o1 += xv * wfs[k * 4 + which * 2 + 1];
        }
        int n = n0 + r;
        if (n < NN) {
            if (which == 0) ((float2*)g_asrc)[n] = make_float2(o0, o1);
            else            ((float2*)g_adst)[n] = make_float2(o0, o1);
        }
    }

    // main GEMM: 4 chunks x 16 nodes, fully unrolled accumulators
    for (int t = 0; t < 4; t++) {
        float acc[16];
#pragma unroll
        for (int i = 0; i < 16; i++) acc[i] = 0.f;
#pragma unroll
        for (int i = 0; i < 16; i++) {
            const float4* xr = (const float4*)&xs[t * 16 + i][0];
#pragma unroll
            for (int k4 = 0; k4 < 16; k4++) {
                float4 v = xr[k4];
                acc[i] += v.x * wreg[k4 * 4] + v.y * wreg[k4 * 4 + 1]
                        + v.z * wreg[k4 * 4 + 2] + v.w * wreg[k4 * 4 + 3];
            }
        }
        int nb = n0 + t * 16;
#pragma unroll
        for (int i = 0; i < 16; i++)
            if (nb + i < NN) g_xl[(nb + i) * HXC + col] = acc[i];
    }
}

// ================= K4: scatter + featatt layer-0 (merged) =================
// blocks 0..FB-1: featatt (128 active threads).  blocks FB..FB+SB-1: scatter.
__global__ void scatfeat_kernel(const int* __restrict__ ei,
                                const float* __restrict__ x,
                                const float* __restrict__ W0) {
    if (blockIdx.x < FB) {
        if (threadIdx.x >= 128) return;   // exited threads excluded from barriers
        featatt_body(x, W0, g_wfold[0], blockIdx.x);
    } else {
        int e = (blockIdx.x - FB) * 256 + threadIdx.x;
        if (e >= ET) return;
        int s, d;
        if (e < EE) { s = ei[e]; d = ei[EE + e]; } else { s = d = e - EE; }
        int pos = atomicAdd(&g_cur[d], 1);
        g_csr[pos] = s;
    }
}

// ================= K7: standalone featatt (layer 1) =================
__global__ void featatt_kernel(const float* __restrict__ x, const float* __restrict__ W) {
    featatt_body(x, W, g_wfold[1], blockIdx.x);
}

// ================= agg: fused softmax + gather aggregation (warp per dst) =================
__global__ void agg_kernel() {
    int warp = (blockIdx.x * blockDim.x + threadIdx.x) >> 5;
    int lane = threadIdx.x & 31;
    if (warp >= NN) return;
    int n = warp;
    int o0 = g_off[n], o1 = g_off[n + 1];
    float2 ad = ((const float2*)g_adst)[n];
    int h = lane >> 4;
    float4 acc = make_float4(0.f, 0.f, 0.f, 0.f);
    float dw0 = 0.f, dw1 = 0.f;
    const float4* xl4 = (const float4*)g_xl;

    for (int base = o0; base < o1; base += 32) {
        int c = min(32, o1 - base);
        int s_l = 0;
        float w0_l = 0.f, w1_l = 0.f;
        if (lane < c) {
            s_l = g_csr[base + lane];
            float2 as = ((const float2*)g_asrc)[s_l];
            w0_l = expf(lrelu(as.x + ad.x));
            w1_l = expf(lrelu(as.y + ad.y));
            dw0 += w0_l; dw1 += w1_l;
        }
        int nIter = (c + 3) & ~3;        // padded lanes: w=0, s=0 (safe)
        for (int j = 0; j < nIter; j += 4) {
            int   s[4];
            float w0[4], w1[4];
#pragma unroll
            for (int u = 0; u < 4; u++) {
                s[u]  = __shfl_sync(0xffffffffu, s_l, j + u);
                w0[u] = __shfl_sync(0xffffffffu, w0_l, j + u);
                w1[u] = __shfl_sync(0xffffffffu, w1_l, j + u);
            }
            float4 v[4];
#pragma unroll
            for (int u = 0; u < 4; u++) v[u] = xl4[s[u] * 32 + lane];
#pragma unroll
            for (int u = 0; u < 4; u++) {
                float w = h ? w1[u] : w0[u];
                acc.x += w * v[u].x; acc.y += w * v[u].y;
                acc.z += w * v[u].z; acc.w += w * v[u].w;
            }
        }
    }
#pragma unroll
    for (int o = 16; o > 0; o >>= 1) {
        dw0 += __shfl_xor_sync(0xffffffffu, dw0, o);
        dw1 += __shfl_xor_sync(0xffffffffu, dw1, o);
    }
    float denom = (h ? dw1 : dw0) + 1e-16f;
    float inv = 1.f / denom;
    ((float4*)g_agg)[n * 32 + lane] =
        make_float4(acc.x * inv, acc.y * inv, acc.z * inv, acc.w * inv);
}

// ================= post: h = elu(agg + bias) @ fcw + fcb =================
__global__ void post_kernel(const float* __restrict__ bias,
                            const float* __restrict__ fcw,
                            const float* __restrict__ fcb) {
    __shared__ float tile[32][128];
    __shared__ float part[32][64];
    int tid = threadIdx.x;
    int n0 = blockIdx.x * 32;
    int col = tid & 63, kh = tid >> 6;
    float fwreg[64];
#pragma unroll
    for (int k = 0; k < 64; k++) fwreg[k] = fcw[(kh * 64 + k) * 64 + col];
    for (int i = tid; i < 32 * 128; i += 128) {
        int r = i >> 7, c = i & 127;
        float v = 0.f;
        if (n0 + r < NN) {
            v = g_agg[(n0 + r) * HXC + c] + bias[c];
            v = (v > 0.f) ? v : expm1f(v);   // ELU
        }
        tile[r][c] = v;
    }
    __syncthreads();
    float b = fcb[col];
    for (int ch = 0; ch < 4; ch++) {
        float acc[8];
#pragma unroll
        for (int j = 0; j < 8; j++) acc[j] = 0.f;
#pragma unroll
        for (int j = 0; j < 8; j++) {
            const float4* tr = (const float4*)&tile[ch * 8 + j][kh * 64];
#pragma unroll
            for (int k4 = 0; k4 < 16; k4++) {
                float4 v = tr[k4];
                acc[j] += v.x * fwreg[k4 * 4] + v.y * fwreg[k4 * 4 + 1]
                        + v.z * fwreg[k4 * 4 + 2] + v.w * fwreg[k4 * 4 + 3];
            }
        }
        if (kh == 1) {
#pragma unroll
            for (int j = 0; j < 8; j++) part[ch * 8 + j][col] = acc[j];
        }
        __syncthreads();
        if (kh == 0) {
#pragma unroll
            for (int j = 0; j < 8; j++) {
                int n = n0 + ch * 8 + j;
                if (n < NN) g_h[n * HIDD + col] = acc[j] + part[ch * 8 + j][col] + b;
            }
        }
    }
}

// ================= postfinal: layer-2 post + logits + gumbel softmax =================
__global__ void postfinal_kernel(const float* __restrict__ bias,
                                 const float* __restrict__ fcw,
                                 const float* __restrict__ fcb,
                                 const float* __restrict__ ow,
                                 const float* __restrict__ ob,
                                 const float* __restrict__ gu,
                                 float* __restrict__ out) {
    __shared__ float tile[32][128];
    __shared__ float part[32][64];
    __shared__ float h_s[32][64];
    __shared__ float ows[64 * 32];
    int tid = threadIdx.x;
    int n0 = blockIdx.x * 32;
    int col = tid & 63, kh = tid >> 6;
    for (int i = tid; i < 64 * 32; i += 128) ows[i] = ow[i];
    float fwreg[64];
#pragma unroll
    for (int k = 0; k < 64; k++) fwreg[k] = fcw[(kh * 64 + k) * 64 + col];
    for (int i = tid; i < 32 * 128; i += 128) {
        int r = i >> 7, c = i & 127;
        float v = 0.f;
        if (n0 + r < NN) {
            v = g_agg[(n0 + r) * HXC + c] + bias[c];
            v = (v > 0.f) ? v : expm1f(v);
        }
        tile[r][c] = v;
    }
    __syncthreads();
    float b = fcb[col];
    for (int ch = 0; ch < 4; ch++) {
        float acc[8];
#pragma unroll
        for (int j = 0; j < 8; j++) acc[j] = 0.f;
#pragma unroll
        for (int j = 0; j < 8; j++) {
            const float4* tr = (const float4*)&tile[ch * 8 + j][kh * 64];
#pragma unroll
            for (int k4 = 0; k4 < 16; k4++) {
                float4 v = tr[k4];
                acc[j] += v.x * fwreg[k4 * 4] + v.y * fwreg[k4 * 4 + 1]
                        + v.z * fwreg[k4 * 4 + 2] + v.w * fwreg[k4 * 4 + 3];
            }
        }
        if (kh == 1) {
#pragma unroll
            for (int j = 0; j < 8; j++) part[ch * 8 + j][col] = acc[j];
        }
        __syncthreads();
        if (kh == 0) {
#pragma unroll
            for (int j = 0; j < 8; j++)
                h_s[ch * 8 + j][col] = acc[j] + part[ch * 8 + j][col] + b;
        }
        __syncthreads();
    }
    int n = tid >> 2, g4 = tid & 3;
    int gn = n0 + n;
    float lg[8];
#pragma unroll
    for (int q = 0; q < 8; q++) lg[q] = ob[g4 * 8 + q];
#pragma unroll
    for (int k = 0; k < 64; k++) {
        float hv = h_s[n][k];
#pragma unroll
        for (int q = 0; q < 8; q++) lg[q] += hv * ows[k * 32 + g4 * 8 + q];
    }
    if (gn < NN) {
        float z[8];
        float m = -FLT_MAX;
#pragma unroll
        for (int q = 0; q < 8; q++) {
            float u = gu[gn * OUTD + g4 * 8 + q];
            float gg = -logf(-logf(u + 1e-20f) + 1e-20f);
            z[q] = lg[q] + gg;
            m = fmaxf(m, z[q]);
        }
        m = fmaxf(m, __shfl_xor_sync(0xffffffffu, m, 1, 4));
        m = fmaxf(m, __shfl_xor_sync(0xffffffffu, m, 2, 4));
        float ssum = 0.f;
        float e[8];
#pragma unroll
        for (int q = 0; q < 8; q++) { e[q] = expf(z[q] - m); ssum += e[q]; }
        ssum += __shfl_xor_sync(0xffffffffu, ssum, 1, 4);
        ssum += __shfl_xor_sync(0xffffffffu, ssum, 2, 4);
        float inv = 1.f / ssum;
#pragma unroll
        for (int q = 0; q < 8; q++) out[gn * OUTD + g4 * 8 + q] = e[q] * inv;
    }
}

// ================= orchestration =================
extern "C" void kernel_launch(void* const* d_in, const int* in_sizes, int n_in,
                              void* d_out, int out_size) {
    const float* x      = (const float*)d_in[0];
    const int*   ei     = (const int*)d_in[1];
    const float* W0     = (const float*)d_in[2];
    const float* asrc0  = (const float*)d_in[3];
    const float* adst0  = (const float*)d_in[4];
    const float* bias0  = (const float*)d_in[5];
    const float* fcw0   = (const float*)d_in[6];
    const float* fcb0   = (const float*)d_in[7];
    const float* W1     = (const float*)d_in[8];
    const float* asrc1  = (const float*)d_in[9];
    const float* adst1  = (const float*)d_in[10];
    const float* bias1  = (const float*)d_in[11];
    const float* fcw1   = (const float*)d_in[12];
    const float* fcb1   = (const float*)d_in[13];
    const float* out_w  = (const float*)d_in[14];
    const float* out_b  = (const float*)d_in[15];
    const float* gu     = (const float*)d_in[16];
    float* out = (float*)d_out;

    float* hin;
    cudaGetSymbolAddress((void**)&hin, g_h);
    int* degp;
    cudaGetSymbolAddress((void**)&degp, g_deg);

    // 1. zero degree counters
    cudaMemsetAsync(degp, 0, NN * sizeof(int));
    // 2. histogram + both folds
    histfold_kernel<<<HB + 2, 256>>>(ei, W0, asrc0, adst0, W1, asrc1, adst1);
    // 3. CSR offsets
    scan_kernel<<<NBLK, SCAN_BLK>>>();
    // 4. scatter + featatt layer 0 (independent, merged)
    scatfeat_kernel<<<FB + SB, 256>>>(ei, x, W0);
    // 5-6. layer 1 remainder
    agg_kernel<<<(NN + 7) / 8, 256>>>();
    post_kernel<<<(NN + 31) / 32, 128>>>(bias0, fcw0, fcb0);
    // 7-9. layer 2 + fused head
    featatt_kernel<<<FB, 128>>>(hin, W1);
    agg_kernel<<<(NN + 7) / 8, 256>>>();
    postfinal_kernel<<<(NN + 31) / 32, 128>>>(bias1, fcw1, fcb1, out_w, out_b, gu, out);
}

// round 10
// speedup vs baseline: 1.4387x; 1.2154x over previous
#include <cuda_runtime.h>
#include <cuda_bf16.h>
#include <cfloat>

// Problem constants (fixed by the dataset)
#define NN 50000
#define EE 800000
#define ET (EE + NN)        // edges + self-loops
#define HXC 128             // H*C = 2*64
#define HIDD 64
#define OUTD 32

#define SCAN_BLK 256
#define NBLK ((NN + SCAN_BLK - 1) / SCAN_BLK)   // 196
#define HB ((EE + 255) / 256)                   // hist blocks
#define SB ((ET + 255) / 256)                   // scatter blocks
#define AB ((NN + 63) / 64)                     // attdot blocks (64 nodes each)

// -------- scratch (device globals; no allocation allowed) --------
__device__ float g_aggx[NN * HXC];   // per-head weighted x sums [N][h0:64|h1:64]
__device__ float g_asrc[NN * 2];     // per-node per-head attention dots
__device__ float g_adst[NN * 2];
__device__ float g_h[NN * HIDD];     // post-FC hidden (layer-1 output)
__device__ float g_wfold[2][64 * 4]; // per-layer W @ [att_src|att_dst] folds
__device__ int   g_deg[NN];
__device__ int   g_off[NN + 1];
__device__ int   g_cur[NN];
__device__ int   g_csr[ET];

__device__ __forceinline__ float lrelu(float x) {
    return (x >= 0.f) ? x : 0.2f * x;
}

// ================= hist + both attention folds (merged) =================
__global__ void histfold_kernel(const int* __restrict__ ei,
                                const float* __restrict__ W0,
                                const float* __restrict__ as0, const float* __restrict__ ad0,
                                const float* __restrict__ W1,
                                const float* __restrict__ as1, const float* __restrict__ ad1) {
    int b = blockIdx.x;
    if (b < 2) {
        const float* W   = b ? W1 : W0;
        const float* as_ = b ? as1 : as0;
        const float* ad_ = b ? ad1 : ad0;
        int t = threadIdx.x;
        int k = t >> 2, j = t & 3;
        int h = j & 1;
        const float* av = (j < 2) ? as_ : ad_;
        float acc = 0.f;
#pragma unroll
        for (int c = 0; c < 64; c++)
            acc += W[k * 128 + h * 64 + c] * av[h * 64 + c];
        g_wfold[b][k * 4 + j] = acc;
    } else {
        int e = (b - 2) * 256 + threadIdx.x;
        if (e < EE) atomicAdd(&g_deg[ei[EE + e]], 1);
    }
}

// ================= single-kernel scan (self-loop folded as deg+1) =================
__global__ void scan_kernel() {
    __shared__ int sh[SCAN_BLK];
    __shared__ int base_sh;
    int t = threadIdx.x;
    int start = blockIdx.x * SCAN_BLK;
    int acc = 0;
    for (int i = t; i < start; i += SCAN_BLK) acc += g_deg[i] + 1;
    sh[t] = acc;
    __syncthreads();
    for (int o = SCAN_BLK / 2; o > 0; o >>= 1) {
        if (t < o) sh[t] += sh[t + o];
        __syncthreads();
    }
    if (t == 0) base_sh = sh[0];
    __syncthreads();
    int base = base_sh;
    __syncthreads();
    int i = start + t;
    int v = (i < NN) ? g_deg[i] + 1 : 0;
    sh[t] = v;
    __syncthreads();
    for (int o = 1; o < SCAN_BLK; o <<= 1) {
        int u = (t >= o) ? sh[t - o] : 0;
        __syncthreads();
        sh[t] += u;
        __syncthreads();
    }
    if (i < NN) {
        int off = base + sh[t] - v;
        g_off[i] = off;
        g_cur[i] = off;
        if (i == NN - 1) g_off[NN] = off + v;
    }
}

// -------- attention dots for 64 nodes from raw features via fold --------
__device__ __forceinline__ void attdot_body(const float* __restrict__ x,
                                            const float* __restrict__ wf,
                                            int bidx) {
    __shared__ float xs[64][65];
    __shared__ float wfs[256];
    int tid = threadIdx.x;   // 128 active
    int n0 = bidx * 64;
    for (int i = tid; i < 64 * 64; i += 128) {
        int r = i >> 6, c = i & 63;
        xs[r][c] = (n0 + r < NN) ? x[(n0 + r) * 64 + c] : 0.f;
    }
    wfs[tid] = wf[tid];
    wfs[tid + 128] = wf[tid + 128];
    __syncthreads();
    int r = tid >> 1, which = tid & 1;
    float o0 = 0.f, o1 = 0.f;
#pragma unroll
    for (int k = 0; k < 64; k++) {
        float xv = xs[r][k];
        o0 += xv * wfs[k * 4 + which * 2 + 0];
        o1 += xv * wfs[k * 4 + which * 2 + 1];
    }
    int n = n0 + r;
    if (n < NN) {
        if (which == 0) ((float2*)g_asrc)[n] = make_float2(o0, o1);
        else            ((float2*)g_adst)[n] = make_float2(o0, o1);
    }
}

// ================= scatter + layer-1 attention dots (merged) =================
__global__ void scatatt_kernel(const int* __restrict__ ei, const float* __restrict__ x) {
    if (blockIdx.x < AB) {
        if (threadIdx.x >= 128) return;   // exited threads excluded from barriers
        attdot_body(x, g_wfold[0], blockIdx.x);
    } else {
        int e = (blockIdx.x - AB) * 256 + threadIdx.x;
        if (e >= ET) return;
        int s, d;
        if (e < EE) { s = ei[e]; d = ei[EE + e]; } else { s = d = e - EE; }
        int pos = atomicAdd(&g_cur[d], 1);
        g_csr[pos] = s;
    }
}

// ================= agg: softmax + raw-x gather (warp per dst, 256B rows) =================
// lane owns one float2 (8B) of the 64-float src row; accumulates BOTH heads.
__global__ void agg_kernel(const float* __restrict__ xin) {
    int warp = (blockIdx.x * blockDim.x + threadIdx.x) >> 5;
    int lane = threadIdx.x & 31;
    if (warp >= NN) return;
    int n = warp;
    int o0 = g_off[n], o1 = g_off[n + 1];
    float2 ad = ((const float2*)g_adst)[n];
    float2 a0 = make_float2(0.f, 0.f), a1 = make_float2(0.f, 0.f);
    float dw0 = 0.f, dw1 = 0.f;
    const float2* x2 = (const float2*)xin;

    for (int base = o0; base < o1; base += 32) {
        int c = min(32, o1 - base);
        int s_l = 0;
        float w0_l = 0.f, w1_l = 0.f;
        if (lane < c) {
            s_l = g_csr[base + lane];
            float2 as = ((const float2*)g_asrc)[s_l];
            w0_l = expf(lrelu(as.x + ad.x));
            w1_l = expf(lrelu(as.y + ad.y));
            dw0 += w0_l; dw1 += w1_l;
        }
        int nIter = (c + 3) & ~3;        // padded lanes: w=0, s=0 (safe)
        for (int j = 0; j < nIter; j += 4) {
            int   s[4];
            float w0[4], w1[4];
#pragma unroll
            for (int u = 0; u < 4; u++) {
                s[u]  = __shfl_sync(0xffffffffu, s_l, j + u);
                w0[u] = __shfl_sync(0xffffffffu, w0_l, j + u);
                w1[u] = __shfl_sync(0xffffffffu, w1_l, j + u);
            }
            float2 v[4];
#pragma unroll
            for (int u = 0; u < 4; u++) v[u] = x2[s[u] * 32 + lane];
#pragma unroll
            for (int u = 0; u < 4; u++) {
                a0.x += w0[u] * v[u].x; a0.y += w0[u] * v[u].y;
                a1.x += w1[u] * v[u].x; a1.y += w1[u] * v[u].y;
            }
        }
    }
#pragma unroll
    for (int o = 16; o > 0; o >>= 1) {
        dw0 += __shfl_xor_sync(0xffffffffu, dw0, o);
        dw1 += __shfl_xor_sync(0xffffffffu, dw1, o);
    }
    float i0 = 1.f / (dw0 + 1e-16f);
    float i1 = 1.f / (dw1 + 1e-16f);
    float2* out2 = (float2*)g_aggx;
    out2[n * 64 + lane]      = make_float2(a0.x * i0, a0.y * i0);
    out2[n * 64 + 32 + lane] = make_float2(a1.x * i1, a1.y * i1);
}

// ================= postW (layer 1): xl = aggx @ W (per head); elu(+bias); @fcw+fcb -> g_h
//                   tail: layer-2 attention dots from the h tile (wfold[1]) =================
__global__ void postW_kernel(const float* __restrict__ W,
                             const float* __restrict__ bias,
                             const float* __restrict__ fcw,
                             const float* __restrict__ fcb) {
    __shared__ float ax[32 * 128];    // 16 KB: aggx tile; later reused for h rows [32*64]
    __shared__ float xl[32][128];     // 16 KB
    __shared__ float part[32][64];    // 8 KB
    __shared__ float wfs[256];
    int tid = threadIdx.x;            // 128
    int n0 = blockIdx.x * 32;
    wfs[tid] = g_wfold[1][tid];
    wfs[tid + 128] = g_wfold[1][tid + 128];
    for (int i = tid; i < 32 * 128; i += 128) {
        int r = i >> 7, c = i & 127;
        ax[r * 128 + c] = (n0 + r < NN) ? g_aggx[(n0 + r) * HXC + c] : 0.f;
    }
    __syncthreads();
    // ---- phase A: xl[r][col] = elu( sum_k ax[r][h*64+k]*W[k][col] + bias[col] ) ----
    {
        int col = tid, h = col >> 6;
        float wA[64];
#pragma unroll
        for (int k = 0; k < 64; k++) wA[k] = W[k * 128 + col];
        float bcol = bias[col];
        for (int ch = 0; ch < 2; ch++) {
            float acc[16];
#pragma unroll
            for (int i = 0; i < 16; i++) acc[i] = 0.f;
#pragma unroll
            for (int i = 0; i < 16; i++) {
                const float4* ar = (const float4*)&ax[(ch * 16 + i) * 128 + h * 64];
#pragma unroll
                for (int k4 = 0; k4 < 16; k4++) {
                    float4 v = ar[k4];
                    acc[i] += v.x * wA[k4 * 4] + v.y * wA[k4 * 4 + 1]
                            + v.z * wA[k4 * 4 + 2] + v.w * wA[k4 * 4 + 3];
                }
            }
#pragma unroll
            for (int i = 0; i < 16; i++) {
                float v = acc[i] + bcol;
                xl[ch * 16 + i][col] = (v > 0.f) ? v : expm1f(v);
            }
        }
    }
    __syncthreads();
    // ---- phase B: h = xl @ fcw + fcb (k split 2 ways over 128 threads) ----
    {
        int col = tid & 63, kh = tid >> 6;
        float fw[64];
#pragma unroll
        for (int k = 0; k < 64; k++) fw[k] = fcw[(kh * 64 + k) * 64 + col];
        float b = fcb[col];
        for (int ch = 0; ch < 4; ch++) {
            float acc[8];
#pragma unroll
            for (int j = 0; j < 8; j++) acc[j] = 0.f;
#pragma unroll
            for (int j = 0; j < 8; j++) {
                const float4* tr = (const float4*)&xl[ch * 8 + j][kh * 64];
#pragma unroll
                for (int k4 = 0; k4 < 16; k4++) {
                    float4 v = tr[k4];
                    acc[j] += v.x * fw[k4 * 4] + v.y * fw[k4 * 4 + 1]
                            + v.z * fw[k4 * 4 + 2] + v.w * fw[k4 * 4 + 3];
                }
            }
            if (kh == 1) {
#pragma unroll
                for (int j = 0; j < 8; j++) part[ch * 8 + j][col] = acc[j];
            }
            __syncthreads();
            if (kh == 0) {
#pragma unroll
                for (int j = 0; j < 8; j++) {
                    int r = ch * 8 + j;
                    float hv = acc[j] + part[r][col] + b;
                    ax[r * 64 + col] = hv;                 // h tile (ax reused)
                    int n = n0 + r;
                    if (n < NN) g_h[n * HIDD + col] = hv;
                }
            }
            __syncthreads();
        }
    }
    // ---- tail: layer-2 attention dots from h tile ----
    {
        int r = tid >> 2, j = tid & 3;   // 32 nodes x 4 outputs
        float o = 0.f;
#pragma unroll
        for (int k = 0; k < 64; k++) o += ax[r * 64 + k] * wfs[k * 4 + j];
        int n = n0 + r;
        if (n < NN) {
            if (j == 0) g_asrc[n * 2 + 0] = o;
            else if (j == 1) g_asrc[n * 2 + 1] = o;
            else if (j == 2) g_adst[n * 2 + 0] = o;
            else             g_adst[n * 2 + 1] = o;
        }
    }
}

// ================= postWfinal (layer 2): + logits + gumbel softmax =================
__global__ void postWfinal_kernel(const float* __restrict__ W,
                                  const float* __restrict__ bias,
                                  const float* __restrict__ fcw,
                                  const float* __restrict__ fcb,
                                  const float* __restrict__ ow,
                                  const float* __restrict__ ob,
                                  const float* __restrict__ gu,
                                  float* __restrict__ out) {
    __shared__ float ax[32 * 128];    // 16 KB; reused for h rows
    __shared__ float xl[32][128];     // 16 KB
    __shared__ float part[32][64];    // 8 KB
    __shared__ float ows[64 * 32];    // 8 KB
    int tid = threadIdx.x;            // 128
    int n0 = blockIdx.x * 32;
    for (int i = tid; i < 64 * 32; i += 128) ows[i] = ow[i];
    for (int i = tid; i < 32 * 128; i += 128) {
        int r = i >> 7, c = i & 127;
        ax[r * 128 + c] = (n0 + r < NN) ? g_aggx[(n0 + r) * HXC + c] : 0.f;
    }
    __syncthreads();
    {
        int col = tid, h = col >> 6;
        float wA[64];
#pragma unroll
        for (int k = 0; k < 64; k++) wA[k] = W[k * 128 + col];
        float bcol = bias[col];
        for (int ch = 0; ch < 2; ch++) {
            float acc[16];
#pragma unroll
            for (int i = 0; i < 16; i++) acc[i] = 0.f;
#pragma unroll
            for (int i = 0; i < 16; i++) {
                const float4* ar = (const float4*)&ax[(ch * 16 + i) * 128 + h * 64];
#pragma unroll
                for (int k4 = 0; k4 < 16; k4++) {
                    float4 v = ar[k4];
                    acc[i] += v.x * wA[k4 * 4] + v.y * wA[k4 * 4 + 1]
                            + v.z * wA[k4 * 4 + 2] + v.w * wA[k4 * 4 + 3];
                }
            }
#pragma unroll
            for (int i = 0; i < 16; i++) {
                float v = acc[i] + bcol;
                xl[ch * 16 + i][col] = (v > 0.f) ? v : expm1f(v);
            }
        }
    }
    __syncthreads();
    {
        int col = tid & 63, kh = tid >> 6;
        float fw[64];
#pragma unroll
        for (int k = 0; k < 64; k++) fw[k] = fcw[(kh * 64 + k) * 64 + col];
        float b = fcb[col];
        for (int ch = 0; ch < 4; ch++) {
            float acc[8];
#pragma unroll
            for (int j = 0; j < 8; j++) acc[j] = 0.f;
#pragma unroll
            for (int j = 0; j < 8; j++) {
                const float4* tr = (const float4*)&xl[ch * 8 + j][kh * 64];
#pragma unroll
                for (int k4 = 0; k4 < 16; k4++) {
                    float4 v = tr[k4];
                    acc[j] += v.x * fw[k4 * 4] + v.y * fw[k4 * 4 + 1]
                            + v.z * fw[k4 * 4 + 2] + v.w * fw[k4 * 4 + 3];
                }
            }
            if (kh == 1) {
#pragma unroll
                for (int j = 0; j < 8; j++) part[ch * 8 + j][col] = acc[j];
            }
            __syncthreads();
            if (kh == 0) {
#pragma unroll
                for (int j = 0; j < 8; j++) {
                    int r = ch * 8 + j;
                    ax[r * 64 + col] = acc[j] + part[r][col] + b;   // h tile
                }
            }
            __syncthreads();
        }
    }
    // ---- head: thread -> node n=tid>>2, cols g4*8..g4*8+7 ----
    int n = tid >> 2, g4 = tid & 3;
    int gn = n0 + n;
    float lg[8];
#pragma unroll
    for (int q = 0; q < 8; q++) lg[q] = ob[g4 * 8 + q];
#pragma unroll
    for (int k = 0; k < 64; k++) {
        float hv = ax[n * 64 + k];
#pragma unroll
        for (int q = 0; q < 8; q++) lg[q] += hv * ows[k * 32 + g4 * 8 + q];
    }
    if (gn < NN) {
        float z[8];
        float m = -FLT_MAX;
#pragma unroll
        for (int q = 0; q < 8; q++) {
            float u = gu[gn * OUTD + g4 * 8 + q];
            float gg = -logf(-logf(u + 1e-20f) + 1e-20f);
            z[q] = lg[q] + gg;
            m = fmaxf(m, z[q]);
        }
        m = fmaxf(m, __shfl_xor_sync(0xffffffffu, m, 1, 4));
        m = fmaxf(m, __shfl_xor_sync(0xffffffffu, m, 2, 4));
        float ssum = 0.f;
        float e[8];
#pragma unroll
        for (int q = 0; q < 8; q++) { e[q] = expf(z[q] - m); ssum += e[q]; }
        ssum += __shfl_xor_sync(0xffffffffu, ssum, 1, 4);
        ssum += __shfl_xor_sync(0xffffffffu, ssum, 2, 4);
        float inv = 1.f / ssum;
#pragma unroll
        for (int q = 0; q < 8; q++) out[gn * OUTD + g4 * 8 + q] = e[q] * inv;
    }
}

// ================= orchestration =================
extern "C" void kernel_launch(void* const* d_in, const int* in_sizes, int n_in,
                              void* d_out, int out_size) {
    const float* x      = (const float*)d_in[0];
    const int*   ei     = (const int*)d_in[1];
    const float* W0     = (const float*)d_in[2];
    const float* asrc0  = (const float*)d_in[3];
    const float* adst0  = (const float*)d_in[4];
    const float* bias0  = (const float*)d_in[5];
    const float* fcw0   = (const float*)d_in[6];
    const float* fcb0   = (const float*)d_in[7];
    const float* W1     = (const float*)d_in[8];
    const float* asrc1  = (const float*)d_in[9];
    const float* adst1  = (const float*)d_in[10];
    const float* bias1  = (const float*)d_in[11];
    const float* fcw1   = (const float*)d_in[12];
    const float* fcb1   = (const float*)d_in[13];
    const float* out_w  = (const float*)d_in[14];
    const float* out_b  = (const float*)d_in[15];
    const float* gu     = (const float*)d_in[16];
    float* out = (float*)d_out;

    float* hin;
    cudaGetSymbolAddress((void**)&hin, g_h);
    int* degp;
    cudaGetSymbolAddress((void**)&degp, g_deg);

    // 1. zero degree counters
    cudaMemsetAsync(degp, 0, NN * sizeof(int));
    // 2. histogram + both folds
    histfold_kernel<<<HB + 2, 256>>>(ei, W0, asrc0, adst0, W1, asrc1, adst1);
    // 3. CSR offsets
    scan_kernel<<<NBLK, SCAN_BLK>>>();
    // 4. scatter + layer-1 attention dots (independent, merged)
    scatatt_kernel<<<AB + SB, 256>>>(ei, x);
    // 5. layer-1 aggregation over raw x
    agg_kernel<<<(NN + 7) / 8, 256>>>(x);
    // 6. layer-1 W-apply + FC (+ layer-2 attention dots fused in tail)
    postW_kernel<<<(NN + 31) / 32, 128>>>(W0, bias0, fcw0, fcb0);
    // 7. layer-2 aggregation over h
    agg_kernel<<<(NN + 7) / 8, 256>>>(hin);
    // 8. layer-2 W-apply + FC + gumbel softmax head
    postWfinal_kernel<<<(NN + 31) / 32, 128>>>(W1, bias1, fcw1, fcb1, out_w, out_b, gu, out);
}

// round 12
// speedup vs baseline: 1.4549x; 1.0112x over previous
#include <cuda_runtime.h>
#include <cuda_bf16.h>
#include <cfloat>

// Problem constants (fixed by the dataset)
#define NN 50000
#define EE 800000
#define ET (EE + NN)        // edges + self-loops
#define HXC 128             // H*C = 2*64
#define HIDD 64
#define OUTD 32

#define SCAN_BLK 256
#define NBLK ((NN + SCAN_BLK - 1) / SCAN_BLK)   // 196
#define HB ((EE + 255) / 256)                   // hist blocks
#define SB ((ET + 255) / 256)                   // scatter blocks
#define AB ((NN + 63) / 64)                     // attdot blocks (64 nodes each)

// -------- scratch (device globals; no allocation allowed) --------
__device__ float g_aggx[NN * HXC];   // per-head weighted x sums [N][h0:64|h1:64]
__device__ float g_asrc[NN * 2];     // per-node per-head attention dots
__device__ float g_adst[NN * 2];
__device__ float g_h[NN * HIDD];     // post-FC hidden (layer-1 output)
__device__ float g_wfold[2][64 * 4]; // per-layer W @ [att_src|att_dst] folds
__device__ int   g_deg[NN];
__device__ int   g_off[NN + 1];
__device__ int   g_cur[NN];
__device__ int   g_csr[ET];

__device__ __forceinline__ float lrelu(float x) {
    return (x >= 0.f) ? x : 0.2f * x;
}

// ================= hist + both attention folds (merged) =================
__global__ void histfold_kernel(const int* __restrict__ ei,
                                const float* __restrict__ W0,
                                const float* __restrict__ as0, const float* __restrict__ ad0,
                                const float* __restrict__ W1,
                                const float* __restrict__ as1, const float* __restrict__ ad1) {
    int b = blockIdx.x;
    if (b < 2) {
        const float* W   = b ? W1 : W0;
        const float* as_ = b ? as1 : as0;
        const float* ad_ = b ? ad1 : ad0;
        int t = threadIdx.x;
        int k = t >> 2, j = t & 3;
        int h = j & 1;
        const float* av = (j < 2) ? as_ : ad_;
        float acc = 0.f;
#pragma unroll
        for (int c = 0; c < 64; c++)
            acc += W[k * 128 + h * 64 + c] * av[h * 64 + c];
        g_wfold[b][k * 4 + j] = acc;
    } else {
        int e = (b - 2) * 256 + threadIdx.x;
        if (e < EE) atomicAdd(&g_deg[ei[EE + e]], 1);
    }
}

// ================= single-kernel scan (self-loop folded as deg+1) =================
__global__ void scan_kernel() {
    __shared__ int sh[SCAN_BLK];
    __shared__ int base_sh;
    int t = threadIdx.x;
    int start = blockIdx.x * SCAN_BLK;
    int acc = 0;
    for (int i = t; i < start; i += SCAN_BLK) acc += g_deg[i] + 1;
    sh[t] = acc;
    __syncthreads();
    for (int o = SCAN_BLK / 2; o > 0; o >>= 1) {
        if (t < o) sh[t] += sh[t + o];
        __syncthreads();
    }
    if (t == 0) base_sh = sh[0];
    __syncthreads();
    int base = base_sh;
    __syncthreads();
    int i = start + t;
    int v = (i < NN) ? g_deg[i] + 1 : 0;
    sh[t] = v;
    __syncthreads();
    for (int o = 1; o < SCAN_BLK; o <<= 1) {
        int u = (t >= o) ? sh[t - o] : 0;
        __syncthreads();
        sh[t] += u;
        __syncthreads();
    }
    if (i < NN) {
        int off = base + sh[t] - v;
        g_off[i] = off;
        g_cur[i] = off;
        if (i == NN - 1) g_off[NN] = off + v;
    }
}

// -------- attention dots for 64 nodes from raw features via fold --------
__device__ __forceinline__ void attdot_body(const float* __restrict__ x,
                                            const float* __restrict__ wf,
                                            int bidx) {
    __shared__ float xs[64][65];
    __shared__ float wfs[256];
    int tid = threadIdx.x;   // 128 active
    int n0 = bidx * 64;
    for (int i = tid; i < 64 * 64; i += 128) {
        int r = i >> 6, c = i & 63;
        xs[r][c] = (n0 + r < NN) ? x[(n0 + r) * 64 + c] : 0.f;
    }
    wfs[tid] = wf[tid];
    wfs[tid + 128] = wf[tid + 128];
    __syncthreads();
    int r = tid >> 1, which = tid & 1;
    float o0 = 0.f, o1 = 0.f;
#pragma unroll
    for (int k = 0; k < 64; k++) {
        float xv = xs[r][k];
        o0 += xv * wfs[k * 4 + which * 2 + 0];
        o1 += xv * wfs[k * 4 + which * 2 + 1];
    }
    int n = n0 + r;
    if (n < NN) {
        if (which == 0) ((float2*)g_asrc)[n] = make_float2(o0, o1);
        else            ((float2*)g_adst)[n] = make_float2(o0, o1);
    }
}

// ================= scatter + layer-1 attention dots (merged) =================
__global__ void scatatt_kernel(const int* __restrict__ ei, const float* __restrict__ x) {
    if (blockIdx.x < AB) {
        if (threadIdx.x >= 128) return;   // exited threads excluded from barriers
        attdot_body(x, g_wfold[0], blockIdx.x);
    } else {
        int e = (blockIdx.x - AB) * 256 + threadIdx.x;
        if (e >= ET) return;
        int s, d;
        if (e < EE) { s = ei[e]; d = ei[EE + e]; } else { s = d = e - EE; }
        int pos = atomicAdd(&g_cur[d], 1);
        g_csr[pos] = s;
    }
}

// ================= agg: softmax + raw-x gather (HALF-WARP per dst) =================
// 16 lanes own the 64-float src row as float4 each; both heads accumulated in-lane.
// All shuffles use the half-warp's own mask: the two halves process different
// nodes with different trip counts, so full-warp masks would be illegal.
__global__ void agg_kernel(const float* __restrict__ xin) {
    int tid = blockIdx.x * blockDim.x + threadIdx.x;
    int n = tid >> 4;                 // half-warp id = node
    int sub = threadIdx.x & 15;       // lane within half-warp
    unsigned hmask = 0xFFFFu << (threadIdx.x & 16);
    if (n >= NN) return;
    int o0 = g_off[n], o1 = g_off[n + 1];
    float2 ad = ((const float2*)g_adst)[n];
    float4 a0 = make_float4(0.f, 0.f, 0.f, 0.f);
    float4 a1 = make_float4(0.f, 0.f, 0.f, 0.f);
    float dw0 = 0.f, dw1 = 0.f;
    const float4* x4 = (const float4*)xin;

    for (int base = o0; base < o1; base += 16) {
        int c = min(16, o1 - base);
        int s_l = 0;
        float w0_l = 0.f, w1_l = 0.f;
        if (sub < c) {
            s_l = g_csr[base + sub];
            float2 as = ((const float2*)g_asrc)[s_l];
            w0_l = expf(lrelu(as.x + ad.x));
            w1_l = expf(lrelu(as.y + ad.y));
            dw0 += w0_l; dw1 += w1_l;
        }
        int nIter = (c + 3) & ~3;        // padded lanes: w=0, s=0 (safe)
        for (int j = 0; j < nIter; j += 4) {
            int   s[4];
            float w0[4], w1[4];
#pragma unroll
            for (int u = 0; u < 4; u++) {
                s[u]  = __shfl_sync(hmask, s_l, j + u, 16);
                w0[u] = __shfl_sync(hmask, w0_l, j + u, 16);
                w1[u] = __shfl_sync(hmask, w1_l, j + u, 16);
            }
            float4 v[4];
#pragma unroll
            for (int u = 0; u < 4; u++) v[u] = x4[s[u] * 16 + sub];
#pragma unroll
            for (int u = 0; u < 4; u++) {
                a0.x += w0[u] * v[u].x; a0.y += w0[u] * v[u].y;
                a0.z += w0[u] * v[u].z; a0.w += w0[u] * v[u].w;
                a1.x += w1[u] * v[u].x; a1.y += w1[u] * v[u].y;
                a1.z += w1[u] * v[u].z; a1.w += w1[u] * v[u].w;
            }
        }
    }
#pragma unroll
    for (int o = 8; o > 0; o >>= 1) {
        dw0 += __shfl_xor_sync(hmask, dw0, o, 16);
        dw1 += __shfl_xor_sync(hmask, dw1, o, 16);
    }
    float i0 = 1.f / (dw0 + 1e-16f);
    float i1 = 1.f / (dw1 + 1e-16f);
    float4* out4 = (float4*)g_aggx;
    out4[n * 32 + sub]      = make_float4(a0.x * i0, a0.y * i0, a0.z * i0, a0.w * i0);
    out4[n * 32 + 16 + sub] = make_float4(a1.x * i1, a1.y * i1, a1.z * i1, a1.w * i1);
}

// ================= postW (layer 1): xl = aggx @ W (per head); elu(+bias); @fcw+fcb -> g_h
//                   tail: layer-2 attention dots from the h tile (wfold[1]) =================
__global__ void postW_kernel(const float* __restrict__ W,
                             const float* __restrict__ bias,
                             const float* __restrict__ fcw,
                             const float* __restrict__ fcb) {
    __shared__ float ax[32 * 128];    // 16 KB: aggx tile; later reused for h rows [32*64]
    __shared__ float xl[32][128];     // 16 KB
    __shared__ float part[32][64];    // 8 KB
    __shared__ float wfs[256];
    int tid = threadIdx.x;            // 128
    int n0 = blockIdx.x * 32;
    wfs[tid] = g_wfold[1][tid];
    wfs[tid + 128] = g_wfold[1][tid + 128];
    for (int i = tid; i < 32 * 128; i += 128) {
        int r = i >> 7, c = i & 127;
        ax[r * 128 + c] = (n0 + r < NN) ? g_aggx[(n0 + r) * HXC + c] : 0.f;
    }
    __syncthreads();
    // ---- phase A: xl[r][col] = elu( sum_k ax[r][h*64+k]*W[k][col] + bias[col] ) ----
    {
        int col = tid, h = col >> 6;
        float wA[64];
#pragma unroll
        for (int k = 0; k < 64; k++) wA[k] = W[k * 128 + col];
        float bcol = bias[col];
        for (int ch = 0; ch < 2; ch++) {
            float acc[16];
#pragma unroll
            for (int i = 0; i < 16; i++) acc[i] = 0.f;
#pragma unroll
            for (int i = 0; i < 16; i++) {
                const float4* ar = (const float4*)&ax[(ch * 16 + i) * 128 + h * 64];
#pragma unroll
                for (int k4 = 0; k4 < 16; k4++) {
                    float4 v = ar[k4];
                    acc[i] += v.x * wA[k4 * 4] + v.y * wA[k4 * 4 + 1]
                            + v.z * wA[k4 * 4 + 2] + v.w * wA[k4 * 4 + 3];
                }
            }
#pragma unroll
            for (int i = 0; i < 16; i++) {
                float v = acc[i] + bcol;
                xl[ch * 16 + i][col] = (v > 0.f) ? v : expm1f(v);
            }
        }
    }
    __syncthreads();
    // ---- phase B: h = xl @ fcw + fcb (k split 2 ways over 128 threads) ----
    {
        int col = tid & 63, kh = tid >> 6;
        float fw[64];
#pragma unroll
        for (int k = 0; k < 64; k++) fw[k] = fcw[(kh * 64 + k) * 64 + col];
        float b = fcb[col];
        for (int ch = 0; ch < 4; ch++) {
            float acc[8];
#pragma unroll
            for (int j = 0; j < 8; j++) acc[j] = 0.f;
#pragma unroll
            for (int j = 0; j < 8; j++) {
                const float4* tr = (const float4*)&xl[ch * 8 + j][kh * 64];
#pragma unroll
                for (int k4 = 0; k4 < 16; k4++) {
                    float4 v = tr[k4];
                    acc[j] += v.x * fw[k4 * 4] + v.y * fw[k4 * 4 + 1]
                            + v.z * fw[k4 * 4 + 2] + v.w * fw[k4 * 4 + 3];
                }
            }
            if (kh == 1) {
#pragma unroll
                for (int j = 0; j < 8; j++) part[ch * 8 + j][col] = acc[j];
            }
            __syncthreads();
            if (kh == 0) {
#pragma unroll
                for (int j = 0; j < 8; j++) {
                    int r = ch * 8 + j;
                    float hv = acc[j] + part[r][col] + b;
                    ax[r * 64 + col] = hv;                 // h tile (ax reused)
                    int n = n0 + r;
                    if (n < NN) g_h[n * HIDD + col] = hv;
                }
            }
            __syncthreads();
        }
    }
    // ---- tail: layer-2 attention dots from h tile ----
    {
        int r = tid >> 2, j = tid & 3;   // 32 nodes x 4 outputs
        float o = 0.f;
#pragma unroll
        for (int k = 0; k < 64; k++) o += ax[r * 64 + k] * wfs[k * 4 + j];
        int n = n0 + r;
        if (n < NN) {
            if (j == 0) g_asrc[n * 2 + 0] = o;
            else if (j == 1) g_asrc[n * 2 + 1] = o;
            else if (j == 2) g_adst[n * 2 + 0] = o;
            else             g_adst[n * 2 + 1] = o;
        }
    }
}

// ================= postWfinal (layer 2): + logits + gumbel softmax =================
__global__ void postWfinal_kernel(const float* __restrict__ W,
                                  const float* __restrict__ bias,
                                  const float* __restrict__ fcw,
                                  const float* __restrict__ fcb,
                                  const float* __restrict__ ow,
                                  const float* __restrict__ ob,
                                  const float* __restrict__ gu,
                                  float* __restrict__ out) {
    __shared__ float ax[32 * 128];    // 16 KB; reused for h rows
    __shared__ float xl[32][128];     // 16 KB
    __shared__ float part[32][64];    // 8 KB
    __shared__ float ows[64 * 32];    // 8 KB
    int tid = threadIdx.x;            // 128
    int n0 = blockIdx.x * 32;
    for (int i = tid; i < 64 * 32; i += 128) ows[i] = ow[i];
    for (int i = tid; i < 32 * 128; i += 128) {
        int r = i >> 7, c = i & 127;
        ax[r * 128 + c] = (n0 + r < NN) ? g_aggx[(n0 + r) * HXC + c] : 0.f;
    }
    __syncthreads();
    {
        int col = tid, h = col >> 6;
        float wA[64];
#pragma unroll
        for (int k = 0; k < 64; k++) wA[k] = W[k * 128 + col];
        float bcol = bias[col];
        for (int ch = 0; ch < 2; ch++) {
            float acc[16];
#pragma unroll
            for (int i = 0; i < 16; i++) acc[i] = 0.f;
#pragma unroll
            for (int i = 0; i < 16; i++) {
                const float4* ar = (const float4*)&ax[(ch * 16 + i) * 128 + h * 64];
#pragma unroll
                for (int k4 = 0; k4 < 16; k4++) {
                    float4 v = ar[k4];
                    acc[i] += v.x * wA[k4 * 4] + v.y * wA[k4 * 4 + 1]
                            + v.z * wA[k4 * 4 + 2] + v.w * wA[k4 * 4 + 3];
                }
            }
#pragma unroll
            for (int i = 0; i < 16; i++) {
                float v = acc[i] + bcol;
                xl[ch * 16 + i][col] = (v > 0.f) ? v : expm1f(v);
            }
        }
    }
    __syncthreads();
    {
        int col = tid & 63, kh = tid >> 6;
        float fw[64];
#pragma unroll
        for (int k = 0; k < 64; k++) fw[k] = fcw[(kh * 64 + k) * 64 + col];
        float b = fcb[col];
        for (int ch = 0; ch < 4; ch++) {
            float acc[8];
#pragma unroll
            for (int j = 0; j < 8; j++) acc[j] = 0.f;
#pragma unroll
            for (int j = 0; j < 8; j++) {
                const float4* tr = (const float4*)&xl[ch * 8 + j][kh * 64];
#pragma unroll
                for (int k4 = 0; k4 < 16; k4++) {
                    float4 v = tr[k4];
                    acc[j] += v.x * fw[k4 * 4] + v.y * fw[k4 * 4 + 1]
                            + v.z * fw[k4 * 4 + 2] + v.w * fw[k4 * 4 + 3];
                }
            }
            if (kh == 1) {
#pragma unroll
                for (int j = 0; j < 8; j++) part[ch * 8 + j][col] = acc[j];
            }
            __syncthreads();
            if (kh == 0) {
#pragma unroll
                for (int j = 0; j < 8; j++) {
                    int r = ch * 8 + j;
                    ax[r * 64 + col] = acc[j] + part[r][col] + b;   // h tile
                }
            }
            __syncthreads();
        }
    }
    // ---- head: thread -> node n=tid>>2, cols g4*8..g4*8+7 ----
    int n = tid >> 2, g4 = tid & 3;
    int gn = n0 + n;
    float lg[8];
#pragma unroll
    for (int q = 0; q < 8; q++) lg[q] = ob[g4 * 8 + q];
#pragma unroll
    for (int k = 0; k < 64; k++) {
        float hv = ax[n * 64 + k];
#pragma unroll
        for (int q = 0; q < 8; q++) lg[q] += hv * ows[k * 32 + g4 * 8 + q];
    }
    if (gn < NN) {
        float z[8];
        float m = -FLT_MAX;
#pragma unroll
        for (int q = 0; q < 8; q++) {
            float u = gu[gn * OUTD + g4 * 8 + q];
            float gg = -logf(-logf(u + 1e-20f) + 1e-20f);
            z[q] = lg[q] + gg;
            m = fmaxf(m, z[q]);
        }
        m = fmaxf(m, __shfl_xor_sync(0xffffffffu, m, 1, 4));
        m = fmaxf(m, __shfl_xor_sync(0xffffffffu, m, 2, 4));
        float ssum = 0.f;
        float e[8];
#pragma unroll
        for (int q = 0; q < 8; q++) { e[q] = expf(z[q] - m); ssum += e[q]; }
        ssum += __shfl_xor_sync(0xffffffffu, ssum, 1, 4);
        ssum += __shfl_xor_sync(0xffffffffu, ssum, 2, 4);
        float inv = 1.f / ssum;
#pragma unroll
        for (int q = 0; q < 8; q++) out[gn * OUTD + g4 * 8 + q] = e[q] * inv;
    }
}

// ================= orchestration =================
extern "C" void kernel_launch(void* const* d_in, const int* in_sizes, int n_in,
                              void* d_out, int out_size) {
    const float* x      = (const float*)d_in[0];
    const int*   ei     = (const int*)d_in[1];
    const float* W0     = (const float*)d_in[2];
    const float* asrc0  = (const float*)d_in[3];
    const float* adst0  = (const float*)d_in[4];
    const float* bias0  = (const float*)d_in[5];
    const float* fcw0   = (const float*)d_in[6];
    const float* fcb0   = (const float*)d_in[7];
    const float* W1     = (const float*)d_in[8];
    const float* asrc1  = (const float*)d_in[9];
    const float* adst1  = (const float*)d_in[10];
    const float* bias1  = (const float*)d_in[11];
    const float* fcw1   = (const float*)d_in[12];
    const float* fcb1   = (const float*)d_in[13];
    const float* out_w  = (const float*)d_in[14];
    const float* out_b  = (const float*)d_in[15];
    const float* gu     = (const float*)d_in[16];
    float* out = (float*)d_out;

    float* hin;
    cudaGetSymbolAddress((void**)&hin, g_h);
    int* degp;
    cudaGetSymbolAddress((void**)&degp, g_deg);

    // 1. zero degree counters
    cudaMemsetAsync(degp, 0, NN * sizeof(int));
    // 2. histogram + both folds
    histfold_kernel<<<HB + 2, 256>>>(ei, W0, asrc0, adst0, W1, asrc1, adst1);
    // 3. CSR offsets
    scan_kernel<<<NBLK, SCAN_BLK>>>();
    // 4. scatter + layer-1 attention dots (independent, merged)
    scatatt_kernel<<<AB + SB, 256>>>(ei, x);
    // 5. layer-1 aggregation over raw x (half-warp per node: 16 threads each)
    agg_kernel<<<(NN * 16 + 255) / 256, 256>>>(x);
    // 6. layer-1 W-apply + FC (+ layer-2 attention dots fused in tail)
    postW_kernel<<<(NN + 31) / 32, 128>>>(W0, bias0, fcw0, fcb0);
    // 7. layer-2 aggregation over h
    agg_kernel<<<(NN * 16 + 255) / 256, 256>>>(hin);
    // 8. layer-2 W-apply + FC + gumbel softmax head
    postWfinal_kernel<<<(NN + 31) / 32, 128>>>(W1, bias1, fcw1, fcb1, out_w, out_b, gu, out);
}